// round 1
// baseline (speedup 1.0000x reference)
#include <cuda_runtime.h>
#include <cuda_bf16.h>
#include <math.h>

// ---------------- problem constants ----------------
#define BATCH   2
#define LSEQ    2048
#define DM      1024        // d_model
#define DI      2048        // d_inner
#define DS      16          // d_state
#define DC      4           // d_conv
#define RANK    64          // dt_rank
#define GDIM    96          // dt_rank + 2*d_state
#define GP      128         // padded GDIM
#define BL      (BATCH*LSEQ)  // 4096

typedef unsigned long long ull;

// ---------------- scratch (device globals, no alloc allowed) ----------------
__device__ float g_xn   [(size_t)BL*DM];     // layernorm output
__device__ float g_xz   [(size_t)BL*2*DI];   // in-proj output (u | z)
__device__ float g_u    [(size_t)BL*DI];     // conv+silu output
__device__ float g_wxp  [(size_t)DI*GP];     // padded W_xproj
__device__ float g_xdbl [(size_t)BL*GP];     // x_dbl (dt | B | C | pad)
__device__ float g_delta[(size_t)BL*DI];     // softplus delta
__device__ float g_yg   [(size_t)BL*DI];     // gated scan output

// ---------------- f32x2 helpers (sm_103a packed fp32 FMA) ----------------
__device__ __forceinline__ ull fma2(ull a, ull b, ull c) {
    ull d;
    asm("fma.rn.f32x2 %0, %1, %2, %3;" : "=l"(d) : "l"(a), "l"(b), "l"(c));
    return d;
}
__device__ __forceinline__ float2 unpack2(ull v) {
    float2 r;
    asm("mov.b64 {%0, %1}, %2;" : "=f"(r.x), "=f"(r.y) : "l"(v));
    return r;
}

// ---------------- layernorm ----------------
__global__ void ln_kernel(const float* __restrict__ x,
                          const float* __restrict__ gamma,
                          const float* __restrict__ beta,
                          float* __restrict__ out) {
    __shared__ float rs[8], rq[8];
    const int row = blockIdx.x;
    const int tid = threadIdx.x;                // 256 threads
    const float* xr = x + (size_t)row * DM;
    float v[4];
    float s = 0.f, s2 = 0.f;
#pragma unroll
    for (int i = 0; i < 4; i++) {
        v[i] = xr[tid + 256 * i];
        s  += v[i];
        s2 += v[i] * v[i];
    }
#pragma unroll
    for (int o = 16; o > 0; o >>= 1) {
        s  += __shfl_xor_sync(0xffffffffu, s,  o);
        s2 += __shfl_xor_sync(0xffffffffu, s2, o);
    }
    if ((tid & 31) == 0) { rs[tid >> 5] = s; rq[tid >> 5] = s2; }
    __syncthreads();
    s = 0.f; s2 = 0.f;
#pragma unroll
    for (int i = 0; i < 8; i++) { s += rs[i]; s2 += rq[i]; }
    const float mean = s * (1.f / DM);
    const float var  = s2 * (1.f / DM) - mean * mean;
    const float rstd = rsqrtf(var + 1e-5f);
    float* orow = out + (size_t)row * DM;
#pragma unroll
    for (int i = 0; i < 4; i++) {
        const int c = tid + 256 * i;
        orow[c] = (v[i] - mean) * rstd * gamma[c] + beta[c];
    }
}

// ---------------- pad W_xproj [DI,96] -> [DI,128] ----------------
__global__ void pad_wxp_kernel(const float* __restrict__ w, float* __restrict__ wp) {
    const int idx = blockIdx.x * blockDim.x + threadIdx.x;   // DI*GP
    const int d = idx >> 7;          // /128
    const int g = idx & (GP - 1);
    wp[idx] = (g < GDIM) ? w[d * GDIM + g] : 0.f;
}

// ---------------- causal depthwise conv (k=4) + SiLU ----------------
__global__ void conv_silu_kernel(const float* __restrict__ xz,
                                 const float* __restrict__ w,
                                 const float* __restrict__ bias,
                                 float* __restrict__ u) {
    const int idx = blockIdx.x * blockDim.x + threadIdx.x;   // BL*DI
    const int d  = idx & (DI - 1);
    const int bl = idx >> 11;                                // /DI
    const int l  = bl & (LSEQ - 1);
    float acc = bias[d];
#pragma unroll
    for (int j = 0; j < DC; j++) {
        const int lj = l - (DC - 1) + j;
        if (lj >= 0)
            acc = fmaf(w[d * DC + j], xz[(size_t)(bl - (DC - 1) + j) * (2 * DI) + d], acc);
    }
    const float sig = 1.f / (1.f + __expf(-acc));
    u[idx] = acc * sig;
}

// ---------------- generic register-blocked SGEMM with FFMA2 inner loop ----
// C[M,N] = A[M,K] @ B[K,N]  (row-major, strides lda/ldb/ldc)
// EPI: 0 = none, 1 = softplus(acc + bias[col]), 2 = acc + E[row*ldc+col]
template <int BM, int BN, int BK, int TM, int TN, int EPI>
__global__ __launch_bounds__((BM / TM) * (BN / TN))
void sgemm_kernel(const float* __restrict__ A, const float* __restrict__ B,
                  float* __restrict__ C, int M, int N, int K,
                  int lda, int ldb, int ldc, const float* __restrict__ E) {
    constexpr int NT = (BM / TM) * (BN / TN);
    constexpr int M2 = TM / 2;
    __shared__ float  As[BK][BM];      // transposed A tile
    __shared__ float2 Bs[BK][BN];      // duplicated B tile (v,v)

    const int tid = threadIdx.x;
    const int rowBase = blockIdx.y * BM;
    const int colBase = blockIdx.x * BN;
    const int tx = tid % (BN / TN);
    const int ty = tid / (BN / TN);
    const int row0 = ty * TM;
    const int col0 = tx * TN;

    ull acc[M2][TN];
#pragma unroll
    for (int m = 0; m < M2; m++)
#pragma unroll
        for (int n = 0; n < TN; n++) acc[m][n] = 0ULL;

    for (int k0 = 0; k0 < K; k0 += BK) {
        // load A tile (transposed into smem)
        for (int f = tid; f < BM * BK / 4; f += NT) {
            const int ar = f / (BK / 4);
            const int ac = (f % (BK / 4)) * 4;
            const float4 v = *(const float4*)(A + (size_t)(rowBase + ar) * lda + k0 + ac);
            As[ac + 0][ar] = v.x; As[ac + 1][ar] = v.y;
            As[ac + 2][ar] = v.z; As[ac + 3][ar] = v.w;
        }
        // load B tile (duplicate each value into float2)
        for (int f = tid; f < BK * BN / 4; f += NT) {
            const int br = f / (BN / 4);
            const int bc = (f % (BN / 4)) * 4;
            const float4 v = *(const float4*)(B + (size_t)(k0 + br) * ldb + colBase + bc);
            Bs[br][bc + 0] = make_float2(v.x, v.x);
            Bs[br][bc + 1] = make_float2(v.y, v.y);
            Bs[br][bc + 2] = make_float2(v.z, v.z);
            Bs[br][bc + 3] = make_float2(v.w, v.w);
        }
        __syncthreads();
#pragma unroll
        for (int k = 0; k < BK; k++) {
            ull a2[M2], b2[TN];
            const ull* ap = (const ull*)(&As[k][row0]);
#pragma unroll
            for (int m = 0; m < M2; m++) a2[m] = ap[m];
            const ull* bp = (const ull*)(&Bs[k][col0]);
#pragma unroll
            for (int n = 0; n < TN; n++) b2[n] = bp[n];
#pragma unroll
            for (int m = 0; m < M2; m++)
#pragma unroll
                for (int n = 0; n < TN; n++)
                    acc[m][n] = fma2(a2[m], b2[n], acc[m][n]);
        }
        __syncthreads();
    }

#pragma unroll
    for (int m = 0; m < M2; m++) {
#pragma unroll
        for (int n = 0; n < TN; n++) {
            const float2 v = unpack2(acc[m][n]);
            const int r = rowBase + row0 + 2 * m;
            const int c = colBase + col0 + n;
            float o0 = v.x, o1 = v.y;
            if (EPI == 1) {
                float t0 = o0 + E[c], t1 = o1 + E[c];
                o0 = (t0 > 20.f) ? t0 : log1pf(__expf(t0));
                o1 = (t1 > 20.f) ? t1 : log1pf(__expf(t1));
            } else if (EPI == 2) {
                o0 += E[(size_t)r * ldc + c];
                o1 += E[(size_t)(r + 1) * ldc + c];
            }
            C[(size_t)r * ldc + c]       = o0;
            C[(size_t)(r + 1) * ldc + c] = o1;
        }
    }
}

// ---------------- selective scan (lane = one (d,n) state) ----------------
// 16 lanes per d-channel, 2 channels per warp, 16 channels per 256-thread block.
__global__ void scan_kernel(const float* __restrict__ delta,
                            const float* __restrict__ u,
                            const float* __restrict__ xdbl,
                            const float* __restrict__ xz,
                            const float* __restrict__ A_log,
                            const float* __restrict__ Dskip,
                            float* __restrict__ yg) {
    const int tid  = threadIdx.x;
    const int warp = tid >> 5;
    const int lane = tid & 31;
    const int n    = lane & 15;
    const int half = lane >> 4;
    const int blocksPerB = DI / 16;                   // 128
    const int b     = blockIdx.x / blocksPerB;
    const int dbase = (blockIdx.x % blocksPerB) * 16;
    const int d     = dbase + warp * 2 + half;

    const float Aval = -__expf(A_log[d * DS + n]);
    const float dsk  = Dskip[d];
    float h = 0.f;
    const size_t base = (size_t)b * LSEQ;

    for (int l = 0; l < LSEQ; l++) {
        const size_t bl = base + l;
        const float dv = delta[bl * DI + d];
        const float uv = u[bl * DI + d];
        const float Bv = xdbl[bl * GP + RANK + n];
        const float Cv = xdbl[bl * GP + RANK + DS + n];
        const float dA = __expf(dv * Aval);
        h = fmaf(dA, h, dv * uv * Bv);
        float yc = h * Cv;
#pragma unroll
        for (int o = 8; o > 0; o >>= 1)
            yc += __shfl_xor_sync(0xffffffffu, yc, o, 16);
        if (n == 0) {
            const float y  = yc + uv * dsk;
            const float zv = xz[bl * (2 * DI) + DI + d];
            const float sig = 1.f / (1.f + __expf(-zv));
            yg[bl * DI + d] = y * (zv * sig);
        }
    }
}

// ---------------- launch ----------------
extern "C" void kernel_launch(void* const* d_in, const int* in_sizes, int n_in,
                              void* d_out, int out_size) {
    const float* x       = (const float*)d_in[0];
    const float* ln_g    = (const float*)d_in[1];
    const float* ln_b    = (const float*)d_in[2];
    const float* W_in    = (const float*)d_in[3];
    const float* conv_w  = (const float*)d_in[4];
    const float* conv_b  = (const float*)d_in[5];
    const float* W_xproj = (const float*)d_in[6];
    const float* W_dt    = (const float*)d_in[7];
    const float* b_dt    = (const float*)d_in[8];
    const float* A_log   = (const float*)d_in[9];
    const float* D_skip  = (const float*)d_in[10];
    const float* W_out   = (const float*)d_in[11];
    float* out = (float*)d_out;

    float *xn, *xz, *u, *wxp, *xdbl, *delta, *yg;
    cudaGetSymbolAddress((void**)&xn,    g_xn);
    cudaGetSymbolAddress((void**)&xz,    g_xz);
    cudaGetSymbolAddress((void**)&u,     g_u);
    cudaGetSymbolAddress((void**)&wxp,   g_wxp);
    cudaGetSymbolAddress((void**)&xdbl,  g_xdbl);
    cudaGetSymbolAddress((void**)&delta, g_delta);
    cudaGetSymbolAddress((void**)&yg,    g_yg);

    // 1) pad W_xproj -> [DI,128]
    pad_wxp_kernel<<<(DI * GP) / 256, 256>>>(W_xproj, wxp);

    // 2) layernorm
    ln_kernel<<<BL, 256>>>(x, ln_g, ln_b, xn);

    // 3) xz = xn @ W_in   [4096,4096] K=1024
    sgemm_kernel<128, 128, 8, 8, 8, 0><<<dim3((2 * DI) / 128, BL / 128), 256>>>(
        xn, W_in, xz, BL, 2 * DI, DM, DM, 2 * DI, 2 * DI, nullptr);

    // 4) conv + silu -> u
    conv_silu_kernel<<<((size_t)BL * DI) / 256, 256>>>(xz, conv_w, conv_b, u);

    // 5) x_dbl = u @ wxp_pad  [4096,128] K=2048 (thin GEMM, small tiles)
    sgemm_kernel<64, 64, 8, 4, 4, 0><<<dim3(GP / 64, BL / 64), 256>>>(
        u, wxp, xdbl, BL, GP, DI, DI, GP, GP, nullptr);

    // 6) delta = softplus(x_dbl[:, :64] @ W_dt + b_dt)  [4096,2048] K=64
    sgemm_kernel<128, 128, 8, 8, 8, 1><<<dim3(DI / 128, BL / 128), 256>>>(
        xdbl, W_dt, delta, BL, DI, RANK, GP, DI, DI, b_dt);

    // 7) selective scan + skip + gate
    scan_kernel<<<BATCH * (DI / 16), 256>>>(delta, u, xdbl, xz, A_log, D_skip, yg);

    // 8) out = x + yg @ W_out  [4096,1024] K=2048
    sgemm_kernel<128, 128, 8, 8, 8, 2><<<dim3(DM / 128, BL / 128), 256>>>(
        yg, W_out, out, BL, DM, DI, DI, DM, DM, x);
}

// round 3
// speedup vs baseline: 2.1099x; 2.1099x over previous
#include <cuda_runtime.h>
#include <cuda_bf16.h>
#include <math.h>
#include <stdint.h>

// ---------------- problem constants ----------------
#define BATCH   2
#define LSEQ    2048
#define DM      1024
#define DI      2048
#define DS      16
#define DC      4
#define RANK    64
#define GDIM    96
#define GP      128
#define BL      (BATCH*LSEQ)  // 4096

// ---------------- scratch ----------------
__device__ float g_xn    [(size_t)BL*DM];
__device__ float g_xz    [(size_t)BL*2*DI];
__device__ float g_u     [(size_t)BL*DI];
__device__ float g_xdbl  [(size_t)BL*GP];
__device__ float g_delta [(size_t)BL*DI];
__device__ float g_yg    [(size_t)BL*DI];
__device__ float g_wt_in [(size_t)(2*DI)*DM];   // [4096,1024]
__device__ float g_wt_out[(size_t)DM*DI];       // [1024,2048]
__device__ float g_wt_xp [(size_t)GP*DI];       // [128,2048] (rows 96..127 zero)
__device__ float g_wt_dt [(size_t)DI*RANK];     // [2048,64]

// ---------------- helpers ----------------
__device__ __forceinline__ uint32_t smem_u32(const void* p) {
    uint32_t a;
    asm("{ .reg .u64 t; cvta.to.shared.u64 t, %1; cvt.u32.u64 %0, t; }" : "=r"(a) : "l"(p));
    return a;
}
__device__ __forceinline__ void cp16(uint32_t dst, const void* src) {
    asm volatile("cp.async.cg.shared.global [%0], [%1], 16;" :: "r"(dst), "l"(src));
}
#define CP_COMMIT() asm volatile("cp.async.commit_group;")
#define CP_WAIT1()  asm volatile("cp.async.wait_group 1;")

__device__ __forceinline__ void mma_tf32(float* c, const uint32_t* a, const uint32_t* b) {
    asm volatile(
        "mma.sync.aligned.m16n8k8.row.col.f32.tf32.tf32.f32 "
        "{%0,%1,%2,%3}, {%4,%5,%6,%7}, {%8,%9}, {%0,%1,%2,%3};"
        : "+f"(c[0]), "+f"(c[1]), "+f"(c[2]), "+f"(c[3])
        : "r"(a[0]), "r"(a[1]), "r"(a[2]), "r"(a[3]), "r"(b[0]), "r"(b[1]));
}

// ---------------- layernorm ----------------
__global__ void ln_kernel(const float* __restrict__ x,
                          const float* __restrict__ gamma,
                          const float* __restrict__ beta,
                          float* __restrict__ out) {
    __shared__ float rs[8], rq[8];
    const int row = blockIdx.x;
    const int tid = threadIdx.x;
    const float* xr = x + (size_t)row * DM;
    float v[4];
    float s = 0.f, s2 = 0.f;
#pragma unroll
    for (int i = 0; i < 4; i++) {
        v[i] = xr[tid + 256 * i];
        s  += v[i];
        s2 += v[i] * v[i];
    }
#pragma unroll
    for (int o = 16; o > 0; o >>= 1) {
        s  += __shfl_xor_sync(0xffffffffu, s,  o);
        s2 += __shfl_xor_sync(0xffffffffu, s2, o);
    }
    if ((tid & 31) == 0) { rs[tid >> 5] = s; rq[tid >> 5] = s2; }
    __syncthreads();
    s = 0.f; s2 = 0.f;
#pragma unroll
    for (int i = 0; i < 8; i++) { s += rs[i]; s2 += rq[i]; }
    const float mean = s * (1.f / DM);
    const float var  = s2 * (1.f / DM) - mean * mean;
    const float rstd = rsqrtf(var + 1e-5f);
    float* orow = out + (size_t)row * DM;
#pragma unroll
    for (int i = 0; i < 4; i++) {
        const int c = tid + 256 * i;
        orow[c] = (v[i] - mean) * rstd * gamma[c] + beta[c];
    }
}

// ---------------- transpose with pad: out[Nout,K] <- in[K,Nsrc] ----------------
__global__ void transpose_pad_kernel(const float* __restrict__ in, float* __restrict__ out,
                                     int K, int Nsrc, int Nout) {
    __shared__ float t[32][33];
    const int kb = blockIdx.x * 32;
    const int nb = blockIdx.y * 32;
    const int tx = threadIdx.x, ty = threadIdx.y;   // 32x8
#pragma unroll
    for (int j = ty; j < 32; j += 8) {
        const int n = nb + tx;
        t[j][tx] = (n < Nsrc) ? in[(size_t)(kb + j) * Nsrc + n] : 0.f;
    }
    __syncthreads();
#pragma unroll
    for (int j = ty; j < 32; j += 8) {
        const int n = nb + j;
        if (n < Nout) out[(size_t)n * K + kb + tx] = t[tx][j];
    }
}

// ---------------- conv + silu ----------------
__global__ void conv_silu_kernel(const float* __restrict__ xz,
                                 const float* __restrict__ w,
                                 const float* __restrict__ bias,
                                 float* __restrict__ u) {
    const int idx = blockIdx.x * blockDim.x + threadIdx.x;
    const int d  = idx & (DI - 1);
    const int bl = idx >> 11;
    const int l  = bl & (LSEQ - 1);
    float acc = bias[d];
#pragma unroll
    for (int j = 0; j < DC; j++) {
        const int lj = l - (DC - 1) + j;
        if (lj >= 0)
            acc = fmaf(w[d * DC + j], xz[(size_t)(bl - (DC - 1) + j) * (2 * DI) + d], acc);
    }
    const float sig = 1.f / (1.f + __expf(-acc));
    u[idx] = acc * sig;
}

// ---------------- tf32 mma.sync GEMM ----------------
// C[M,N] = A[M,K] @ Bt[N,K]^T ; all row-major fp32.
// EPI: 0 none | 1 softplus(acc + E[col]) | 2 acc + E[row*ldc+col]
// Layout: A/B rows in smem with 36-float pitch -> all fragment LDS conflict-free.
template <int EPI>
__global__ __launch_bounds__(256, 1)
void mma_gemm_kernel(const float* __restrict__ A, const float* __restrict__ Bt,
                     float* __restrict__ C, int M, int N, int K,
                     int lda, int ldb, int ldc, const float* __restrict__ E) {
    constexpr int BM = 128, BN = 128, BK = 32;
    constexpr int PITCH = 36;                        // floats per smem row
    constexpr int ROWS_STAGE = BM + BN;              // 256 rows
    constexpr int STAGE_FLOATS = ROWS_STAGE * PITCH; // 9216
    constexpr int STAGES = 3;

    extern __shared__ float smem[];
    const uint32_t smem_b = smem_u32(smem);

    const int tid  = threadIdx.x;
    const int wid  = tid >> 5;
    const int lane = tid & 31;
    const int g    = lane >> 2;       // group 0..7
    const int t    = lane & 3;        // quad 0..3

    const int warpRow = wid & 1;      // 2
    const int warpCol = wid >> 1;     // 4
    const int rowBase = blockIdx.y * BM;
    const int colBase = blockIdx.x * BN;

    float acc[4][4][4];               // [mt][nt][frag]
#pragma unroll
    for (int i = 0; i < 4; i++)
#pragma unroll
        for (int j = 0; j < 4; j++)
#pragma unroll
            for (int q = 0; q < 4; q++) acc[i][j][q] = 0.f;

    const int nchunk = K / BK;

    // stage loader: each thread copies 8 x 16B (A: 128 rows x 8, B: 128 rows x 8)
    auto load_stage = [&](int kc, int s) {
        if (kc < nchunk) {
            const uint32_t base = smem_b + (uint32_t)s * STAGE_FLOATS * 4;
            {   // A rows
                const int r  = tid >> 1;            // 0..127
                const int h  = tid & 1;             // half-row: 4 x16B
                const float* src = A + (size_t)(rowBase + r) * lda + kc * BK + h * 16;
                const uint32_t dst = base + (uint32_t)r * PITCH * 4 + h * 64;
#pragma unroll
                for (int j = 0; j < 4; j++) cp16(dst + j * 16, src + j * 4);
            }
            {   // B rows
                const int r = tid >> 1;
                const int h = tid & 1;
                const float* src = Bt + (size_t)(colBase + r) * ldb + kc * BK + h * 16;
                const uint32_t dst = base + (uint32_t)(BM + r) * PITCH * 4 + h * 64;
#pragma unroll
                for (int j = 0; j < 4; j++) cp16(dst + j * 16, src + j * 4);
            }
        }
        CP_COMMIT();
    };

    load_stage(0, 0);
    load_stage(1, 1);

    for (int i = 0; i < nchunk; i++) {
        CP_WAIT1();
        __syncthreads();
        load_stage(i + 2, (i + 2) % STAGES);

        const float* sa = smem + (i % STAGES) * STAGE_FLOATS + (warpRow * 64) * PITCH;
        const float* sb = smem + (i % STAGES) * STAGE_FLOATS + (BM + warpCol * 32) * PITCH;

#pragma unroll
        for (int ks = 0; ks < 4; ks++) {
            const int k0 = ks * 8;
            uint32_t afr[4][4], bfr[4][2];
#pragma unroll
            for (int mt = 0; mt < 4; mt++) {
                const float* ap = sa + (mt * 16 + g) * PITCH + k0 + t;
                afr[mt][0] = __float_as_uint(ap[0]);
                afr[mt][1] = __float_as_uint(ap[8 * PITCH]);
                afr[mt][2] = __float_as_uint(ap[4]);
                afr[mt][3] = __float_as_uint(ap[8 * PITCH + 4]);
            }
#pragma unroll
            for (int nt = 0; nt < 4; nt++) {
                const float* bp = sb + (nt * 8 + g) * PITCH + k0 + t;
                bfr[nt][0] = __float_as_uint(bp[0]);
                bfr[nt][1] = __float_as_uint(bp[4]);
            }
#pragma unroll
            for (int mt = 0; mt < 4; mt++)
#pragma unroll
                for (int nt = 0; nt < 4; nt++)
                    mma_tf32(acc[mt][nt], afr[mt], bfr[nt]);
        }
        __syncthreads();
    }

    // ---------------- epilogue ----------------
    const int rW = rowBase + warpRow * 64;
    const int cW = colBase + warpCol * 32;
#pragma unroll
    for (int mt = 0; mt < 4; mt++) {
#pragma unroll
        for (int nt = 0; nt < 4; nt++) {
            const int r0 = rW + mt * 16 + g;
            const int r1 = r0 + 8;
            const int c0 = cW + nt * 8 + 2 * t;
            float v0 = acc[mt][nt][0], v1 = acc[mt][nt][1];
            float v2 = acc[mt][nt][2], v3 = acc[mt][nt][3];
            if (EPI == 1) {
                const float b0 = E[c0], b1 = E[c0 + 1];
                float t0 = v0 + b0, t1 = v1 + b1, t2 = v2 + b0, t3 = v3 + b1;
                v0 = (t0 > 20.f) ? t0 : log1pf(__expf(t0));
                v1 = (t1 > 20.f) ? t1 : log1pf(__expf(t1));
                v2 = (t2 > 20.f) ? t2 : log1pf(__expf(t2));
                v3 = (t3 > 20.f) ? t3 : log1pf(__expf(t3));
            } else if (EPI == 2) {
                const float2 e0 = *(const float2*)(E + (size_t)r0 * ldc + c0);
                const float2 e1 = *(const float2*)(E + (size_t)r1 * ldc + c0);
                v0 += e0.x; v1 += e0.y; v2 += e1.x; v3 += e1.y;
            }
            *(float2*)(C + (size_t)r0 * ldc + c0) = make_float2(v0, v1);
            *(float2*)(C + (size_t)r1 * ldc + c0) = make_float2(v2, v3);
        }
    }
}

// ---------------- selective scan ----------------
__global__ void scan_kernel(const float* __restrict__ delta,
                            const float* __restrict__ u,
                            const float* __restrict__ xdbl,
                            const float* __restrict__ xz,
                            const float* __restrict__ A_log,
                            const float* __restrict__ Dskip,
                            float* __restrict__ yg) {
    const int tid  = threadIdx.x;
    const int warp = tid >> 5;
    const int lane = tid & 31;
    const int n    = lane & 15;
    const int half = lane >> 4;
    const int blocksPerB = DI / 16;
    const int b     = blockIdx.x / blocksPerB;
    const int dbase = (blockIdx.x % blocksPerB) * 16;
    const int d     = dbase + warp * 2 + half;

    const float Aval = -__expf(A_log[d * DS + n]);
    const float dsk  = Dskip[d];
    float h = 0.f;
    const size_t base = (size_t)b * LSEQ;

    for (int l = 0; l < LSEQ; l++) {
        const size_t bl = base + l;
        const float dv = delta[bl * DI + d];
        const float uv = u[bl * DI + d];
        const float Bv = xdbl[bl * GP + RANK + n];
        const float Cv = xdbl[bl * GP + RANK + DS + n];
        const float dA = __expf(dv * Aval);
        h = fmaf(dA, h, dv * uv * Bv);
        float yc = h * Cv;
#pragma unroll
        for (int o = 8; o > 0; o >>= 1)
            yc += __shfl_xor_sync(0xffffffffu, yc, o, 16);
        if (n == 0) {
            const float y  = yc + uv * dsk;
            const float zv = xz[bl * (2 * DI) + DI + d];
            const float sig = 1.f / (1.f + __expf(-zv));
            yg[bl * DI + d] = y * (zv * sig);
        }
    }
}

// ---------------- launch ----------------
extern "C" void kernel_launch(void* const* d_in, const int* in_sizes, int n_in,
                              void* d_out, int out_size) {
    const float* x       = (const float*)d_in[0];
    const float* ln_g    = (const float*)d_in[1];
    const float* ln_b    = (const float*)d_in[2];
    const float* W_in    = (const float*)d_in[3];
    const float* conv_w  = (const float*)d_in[4];
    const float* conv_b  = (const float*)d_in[5];
    const float* W_xproj = (const float*)d_in[6];
    const float* W_dt    = (const float*)d_in[7];
    const float* b_dt    = (const float*)d_in[8];
    const float* A_log   = (const float*)d_in[9];
    const float* D_skip  = (const float*)d_in[10];
    const float* W_out   = (const float*)d_in[11];
    float* out = (float*)d_out;

    float *xn, *xz, *u, *xdbl, *delta, *yg, *wtin, *wtout, *wtxp, *wtdt;
    cudaGetSymbolAddress((void**)&xn,    g_xn);
    cudaGetSymbolAddress((void**)&xz,    g_xz);
    cudaGetSymbolAddress((void**)&u,     g_u);
    cudaGetSymbolAddress((void**)&xdbl,  g_xdbl);
    cudaGetSymbolAddress((void**)&delta, g_delta);
    cudaGetSymbolAddress((void**)&yg,    g_yg);
    cudaGetSymbolAddress((void**)&wtin,  g_wt_in);
    cudaGetSymbolAddress((void**)&wtout, g_wt_out);
    cudaGetSymbolAddress((void**)&wtxp,  g_wt_xp);
    cudaGetSymbolAddress((void**)&wtdt,  g_wt_dt);

    const int smemBytes = 3 * 256 * 36 * 4;   // 110592
    cudaFuncSetAttribute(mma_gemm_kernel<0>, cudaFuncAttributeMaxDynamicSharedMemorySize, smemBytes);
    cudaFuncSetAttribute(mma_gemm_kernel<1>, cudaFuncAttributeMaxDynamicSharedMemorySize, smemBytes);
    cudaFuncSetAttribute(mma_gemm_kernel<2>, cudaFuncAttributeMaxDynamicSharedMemorySize, smemBytes);

    dim3 tb(32, 8);
    transpose_pad_kernel<<<dim3(DM / 32, (2 * DI) / 32), tb>>>(W_in,    wtin,  DM, 2 * DI, 2 * DI);
    transpose_pad_kernel<<<dim3(DI / 32, DM / 32),       tb>>>(W_out,   wtout, DI, DM,     DM);
    transpose_pad_kernel<<<dim3(DI / 32, GP / 32),       tb>>>(W_xproj, wtxp,  DI, GDIM,   GP);
    transpose_pad_kernel<<<dim3(RANK / 32, DI / 32),     tb>>>(W_dt,    wtdt,  RANK, DI,   DI);

    ln_kernel<<<BL, 256>>>(x, ln_g, ln_b, xn);

    // xz = xn @ W_in : M=4096 N=4096 K=1024
    mma_gemm_kernel<0><<<dim3((2 * DI) / 128, BL / 128), 256, smemBytes>>>(
        xn, wtin, xz, BL, 2 * DI, DM, DM, DM, 2 * DI, nullptr);

    conv_silu_kernel<<<((size_t)BL * DI) / 256, 256>>>(xz, conv_w, conv_b, u);

    // x_dbl = u @ W_xproj(pad) : M=4096 N=128 K=2048
    mma_gemm_kernel<0><<<dim3(GP / 128, BL / 128), 256, smemBytes>>>(
        u, wtxp, xdbl, BL, GP, DI, DI, DI, GP, nullptr);

    // delta = softplus(x_dbl[:, :64] @ W_dt + b_dt) : M=4096 N=2048 K=64
    mma_gemm_kernel<1><<<dim3(DI / 128, BL / 128), 256, smemBytes>>>(
        xdbl, wtdt, delta, BL, DI, RANK, GP, RANK, DI, b_dt);

    scan_kernel<<<BATCH * (DI / 16), 256>>>(delta, u, xdbl, xz, A_log, D_skip, yg);

    // out = x + yg @ W_out : M=4096 N=1024 K=2048
    mma_gemm_kernel<2><<<dim3(DM / 128, BL / 128), 256, smemBytes>>>(
        yg, wtout, out, BL, DM, DI, DI, DI, DM, x);
}

// round 4
// speedup vs baseline: 4.4170x; 2.0935x over previous
#include <cuda_runtime.h>
#include <cuda_bf16.h>
#include <math.h>
#include <stdint.h>

// ---------------- problem constants ----------------
#define BATCH   2
#define LSEQ    2048
#define DM      1024
#define DI      2048
#define DS      16
#define DC      4
#define RANK    64
#define GDIM    96
#define GP      128
#define BL      (BATCH*LSEQ)  // 4096
#define SPLITK  4

// ---------------- scratch ----------------
__device__ __nv_bfloat16 g_xn_bf [(size_t)BL*DM];
__device__ float         g_xz    [(size_t)BL*2*DI];
__device__ float         g_u     [(size_t)BL*DI];
__device__ __nv_bfloat16 g_u_bf  [(size_t)BL*DI];
__device__ float         g_part  [(size_t)SPLITK*BL*GP];
__device__ float         g_xdbl  [(size_t)BL*GP];
__device__ __nv_bfloat16 g_dt_bf [(size_t)BL*RANK];
__device__ float         g_delta [(size_t)BL*DI];
__device__ __nv_bfloat16 g_yg_bf [(size_t)BL*DI];
__device__ __nv_bfloat16 g_wt_in [(size_t)(2*DI)*DM];   // [4096,1024]
__device__ __nv_bfloat16 g_wt_out[(size_t)DM*DI];       // [1024,2048]
__device__ __nv_bfloat16 g_wt_xp [(size_t)GP*DI];       // [128,2048]
__device__ __nv_bfloat16 g_wt_dt [(size_t)DI*RANK];     // [2048,64]

// ---------------- helpers ----------------
__device__ __forceinline__ uint32_t smem_u32(const void* p) {
    uint32_t a;
    asm("{ .reg .u64 t; cvta.to.shared.u64 t, %1; cvt.u32.u64 %0, t; }" : "=r"(a) : "l"(p));
    return a;
}
__device__ __forceinline__ void cp16(uint32_t dst, const void* src) {
    asm volatile("cp.async.cg.shared.global [%0], [%1], 16;" :: "r"(dst), "l"(src));
}
#define CP_COMMIT() asm volatile("cp.async.commit_group;")
#define CP_WAIT2()  asm volatile("cp.async.wait_group 2;")

__device__ __forceinline__ void mma_bf16(float* c, const uint32_t* a, const uint32_t* b) {
    asm volatile(
        "mma.sync.aligned.m16n8k16.row.col.f32.bf16.bf16.f32 "
        "{%0,%1,%2,%3}, {%4,%5,%6,%7}, {%8,%9}, {%0,%1,%2,%3};"
        : "+f"(c[0]), "+f"(c[1]), "+f"(c[2]), "+f"(c[3])
        : "r"(a[0]), "r"(a[1]), "r"(a[2]), "r"(a[3]), "r"(b[0]), "r"(b[1]));
}
__device__ __forceinline__ float softplus_f(float t) {
    return (t > 20.f) ? t : __logf(1.f + __expf(t));
}

// ---------------- layernorm -> bf16 ----------------
__global__ void ln_kernel(const float* __restrict__ x,
                          const float* __restrict__ gamma,
                          const float* __restrict__ beta,
                          __nv_bfloat16* __restrict__ out) {
    __shared__ float rs[8], rq[8];
    const int row = blockIdx.x;
    const int tid = threadIdx.x;
    const float* xr = x + (size_t)row * DM;
    float v[4];
    float s = 0.f, s2 = 0.f;
#pragma unroll
    for (int i = 0; i < 4; i++) {
        v[i] = xr[tid + 256 * i];
        s  += v[i];
        s2 += v[i] * v[i];
    }
#pragma unroll
    for (int o = 16; o > 0; o >>= 1) {
        s  += __shfl_xor_sync(0xffffffffu, s,  o);
        s2 += __shfl_xor_sync(0xffffffffu, s2, o);
    }
    if ((tid & 31) == 0) { rs[tid >> 5] = s; rq[tid >> 5] = s2; }
    __syncthreads();
    s = 0.f; s2 = 0.f;
#pragma unroll
    for (int i = 0; i < 8; i++) { s += rs[i]; s2 += rq[i]; }
    const float mean = s * (1.f / DM);
    const float var  = s2 * (1.f / DM) - mean * mean;
    const float rstd = rsqrtf(var + 1e-5f);
    __nv_bfloat16* orow = out + (size_t)row * DM;
#pragma unroll
    for (int i = 0; i < 4; i++) {
        const int c = tid + 256 * i;
        orow[c] = __float2bfloat16((v[i] - mean) * rstd * gamma[c] + beta[c]);
    }
}

// ---------------- transpose fp32 -> bf16 : out[Nout,K] <- in[K,Nsrc] --------
__global__ void transpose_bf_kernel(const float* __restrict__ in,
                                    __nv_bfloat16* __restrict__ out,
                                    int K, int Nsrc, int Nout) {
    __shared__ float t[32][33];
    const int kb = blockIdx.x * 32;
    const int nb = blockIdx.y * 32;
    const int tx = threadIdx.x, ty = threadIdx.y;
#pragma unroll
    for (int j = ty; j < 32; j += 8) {
        const int n = nb + tx;
        t[j][tx] = (n < Nsrc) ? in[(size_t)(kb + j) * Nsrc + n] : 0.f;
    }
    __syncthreads();
#pragma unroll
    for (int j = ty; j < 32; j += 8) {
        const int n = nb + j;
        if (n < Nout) out[(size_t)n * K + kb + tx] = __float2bfloat16(t[tx][j]);
    }
}

// ---------------- conv + silu : fp32 + bf16 out ----------------
__global__ void conv_silu_kernel(const float* __restrict__ xz,
                                 const float* __restrict__ w,
                                 const float* __restrict__ bias,
                                 float* __restrict__ u,
                                 __nv_bfloat16* __restrict__ ubf) {
    const int idx = blockIdx.x * blockDim.x + threadIdx.x;
    const int d  = idx & (DI - 1);
    const int bl = idx >> 11;
    const int l  = bl & (LSEQ - 1);
    float acc = bias[d];
#pragma unroll
    for (int j = 0; j < DC; j++) {
        const int lj = l - (DC - 1) + j;
        if (lj >= 0)
            acc = fmaf(w[d * DC + j], xz[(size_t)(bl - (DC - 1) + j) * (2 * DI) + d], acc);
    }
    const float sig = 1.f / (1.f + __expf(-acc));
    const float r = acc * sig;
    u[idx]   = r;
    ubf[idx] = __float2bfloat16(r);
}

// ---------------- bf16 mma.sync GEMM ----------------
// C[M,N] = A[M,K] @ Bt[N,K]^T ; A,Bt bf16 row-major; C fp32 row-major.
// grid.z = K-splits; each split computes Kloc cols starting at z*Kloc, writes
// C + z*partStride. EPI: 0 none | 1 softplus(acc+E[col]) | 2 acc+E[r*ldc+c]
template <int EPI>
__global__ __launch_bounds__(256, 1)
void mma_gemm_kernel(const __nv_bfloat16* __restrict__ A,
                     const __nv_bfloat16* __restrict__ Bt,
                     float* __restrict__ C, int M, int N,
                     int lda, int ldb, int ldc, const float* __restrict__ E,
                     int Kloc, size_t partStride) {
    constexpr int BM = 128, BN = 128, BK = 64;
    constexpr int STAGE_BYTES = 2 * 128 * 128;     // A 16KB + B 16KB
    constexpr int STAGES = 4;

    extern __shared__ __align__(1024) char smem[];
    const uint32_t smem_b = smem_u32(smem);

    const int tid  = threadIdx.x;
    const int wid  = tid >> 5;
    const int lane = tid & 31;
    const int g    = lane >> 2;       // 0..7
    const int t    = lane & 3;        // 0..3

    const int warpRow = wid & 1;      // 2
    const int warpCol = wid >> 1;     // 4
    const int rowBase = blockIdx.y * BM;
    const int colBase = blockIdx.x * BN;
    const int kbase   = blockIdx.z * Kloc;
    C += (size_t)blockIdx.z * partStride;

    float acc[4][4][4];
#pragma unroll
    for (int i = 0; i < 4; i++)
#pragma unroll
        for (int j = 0; j < 4; j++)
#pragma unroll
            for (int q = 0; q < 4; q++) acc[i][j][q] = 0.f;

    const int nchunk = Kloc / BK;

    // loader: per iter a warp covers 4 rows (8x16B per row, XOR-swizzled)
    auto load_stage = [&](int kc, int s) {
        if (kc < nchunk) {
            const uint32_t base = smem_b + (uint32_t)s * STAGE_BYTES;
            const int rw = wid * 4 + (lane >> 3);   // row within 32-row group
            const int un = lane & 7;                // 16B unit
#pragma unroll
            for (int it = 0; it < 4; it++) {
                const int r = it * 32 + rw;
                const uint32_t sw = (uint32_t)((un ^ (r & 7)) << 4);
                cp16(base + (uint32_t)r * 128 + sw,
                     A + (size_t)(rowBase + r) * lda + kbase + kc * BK + un * 8);
                cp16(base + 16384u + (uint32_t)r * 128 + sw,
                     Bt + (size_t)(colBase + r) * ldb + kbase + kc * BK + un * 8);
            }
        }
        CP_COMMIT();
    };

    load_stage(0, 0);
    load_stage(1, 1);
    load_stage(2, 2);

    for (int i = 0; i < nchunk; i++) {
        CP_WAIT2();
        __syncthreads();
        load_stage(i + 3, (i + 3) & 3);

        const char* st = smem + (i & 3) * STAGE_BYTES;
        const char* pa = st + ((warpRow * 64 + g) * 128) + 4 * t;
        const char* pb = st + 16384 + ((warpCol * 32 + g) * 128) + 4 * t;

#pragma unroll
        for (int ks = 0; ks < 4; ks++) {
            const int ku = ks * 2;                  // base 16B-unit of this k16
            uint32_t afr[4][4], bfr[4][2];
#pragma unroll
            for (int mt = 0; mt < 4; mt++) {
                const char* p0 = pa + (mt * 16) * 128;
                afr[mt][0] = *(const uint32_t*)(p0 + (((ku)     ^ g) << 4));
                afr[mt][1] = *(const uint32_t*)(p0 + 8 * 128 + (((ku)     ^ g) << 4));
                afr[mt][2] = *(const uint32_t*)(p0 + (((ku + 1) ^ g) << 4));
                afr[mt][3] = *(const uint32_t*)(p0 + 8 * 128 + (((ku + 1) ^ g) << 4));
            }
#pragma unroll
            for (int nt = 0; nt < 4; nt++) {
                const char* p0 = pb + (nt * 8) * 128;
                bfr[nt][0] = *(const uint32_t*)(p0 + (((ku)     ^ g) << 4));
                bfr[nt][1] = *(const uint32_t*)(p0 + (((ku + 1) ^ g) << 4));
            }
#pragma unroll
            for (int mt = 0; mt < 4; mt++)
#pragma unroll
                for (int nt = 0; nt < 4; nt++)
                    mma_bf16(acc[mt][nt], afr[mt], bfr[nt]);
        }
        __syncthreads();
    }

    // ---------------- epilogue ----------------
    const int rW = rowBase + warpRow * 64;
    const int cW = colBase + warpCol * 32;
#pragma unroll
    for (int mt = 0; mt < 4; mt++) {
#pragma unroll
        for (int nt = 0; nt < 4; nt++) {
            const int r0 = rW + mt * 16 + g;
            const int r1 = r0 + 8;
            const int c0 = cW + nt * 8 + 2 * t;
            float v0 = acc[mt][nt][0], v1 = acc[mt][nt][1];
            float v2 = acc[mt][nt][2], v3 = acc[mt][nt][3];
            if (EPI == 1) {
                const float b0 = E[c0], b1 = E[c0 + 1];
                v0 = softplus_f(v0 + b0);
                v1 = softplus_f(v1 + b1);
                v2 = softplus_f(v2 + b0);
                v3 = softplus_f(v3 + b1);
            } else if (EPI == 2) {
                const float2 e0 = *(const float2*)(E + (size_t)r0 * ldc + c0);
                const float2 e1 = *(const float2*)(E + (size_t)r1 * ldc + c0);
                v0 += e0.x; v1 += e0.y; v2 += e1.x; v3 += e1.y;
            }
            *(float2*)(C + (size_t)r0 * ldc + c0) = make_float2(v0, v1);
            *(float2*)(C + (size_t)r1 * ldc + c0) = make_float2(v2, v3);
        }
    }
}

// ---------------- split-K reduce + dt->bf16 ----------------
__global__ void reduce_xdbl_kernel(const float* __restrict__ part,
                                   float* __restrict__ xdbl,
                                   __nv_bfloat16* __restrict__ dtbf) {
    const int idx = blockIdx.x * blockDim.x + threadIdx.x;     // BL*GP
    const size_t S = (size_t)BL * GP;
    float s = part[idx] + part[idx + S] + part[idx + 2 * S] + part[idx + 3 * S];
    xdbl[idx] = s;
    const int col = idx & (GP - 1);
    if (col < RANK) dtbf[(size_t)(idx >> 7) * RANK + col] = __float2bfloat16(s);
}

// ---------------- selective scan (prefetched) ----------------
__global__ void scan_kernel(const float* __restrict__ delta,
                            const float* __restrict__ u,
                            const float* __restrict__ xdbl,
                            const float* __restrict__ xz,
                            const float* __restrict__ A_log,
                            const float* __restrict__ Dskip,
                            __nv_bfloat16* __restrict__ yg) {
    const int tid  = threadIdx.x;
    const int warp = tid >> 5;
    const int lane = tid & 31;
    const int n    = lane & 15;
    const int half = lane >> 4;
    const int blocksPerB = DI / 16;
    const int b     = blockIdx.x / blocksPerB;
    const int dbase = (blockIdx.x % blocksPerB) * 16;
    const int d     = dbase + warp * 2 + half;

    const float Aval = -__expf(A_log[d * DS + n]);
    const float dsk  = Dskip[d];
    float h = 0.f;
    const size_t base = (size_t)b * LSEQ;

    size_t p  = base * DI + d;
    size_t px = base * GP;
    float dv = delta[p];
    float uv = u[p];
    float Bv = xdbl[px + RANK + n];
    float Cv = xdbl[px + RANK + DS + n];
    float zv = xz[(base) * (2 * DI) + DI + d];

    for (int l = 0; l < LSEQ; l++) {
        float dv2, uv2, Bv2, Cv2, zv2;
        if (l + 1 < LSEQ) {
            dv2 = delta[p + DI];
            uv2 = u[p + DI];
            Bv2 = xdbl[px + GP + RANK + n];
            Cv2 = xdbl[px + GP + RANK + DS + n];
            zv2 = xz[(base + l + 1) * (2 * DI) + DI + d];
        }
        const float dA = __expf(dv * Aval);
        h = fmaf(dA, h, dv * uv * Bv);
        float yc = h * Cv;
#pragma unroll
        for (int o = 8; o > 0; o >>= 1)
            yc += __shfl_xor_sync(0xffffffffu, yc, o, 16);
        if (n == 0) {
            const float y   = yc + uv * dsk;
            const float sig = 1.f / (1.f + __expf(-zv));
            yg[(base + l) * DI + d] = __float2bfloat16(y * (zv * sig));
        }
        p += DI; px += GP;
        dv = dv2; uv = uv2; Bv = Bv2; Cv = Cv2; zv = zv2;
    }
}

// ---------------- launch ----------------
extern "C" void kernel_launch(void* const* d_in, const int* in_sizes, int n_in,
                              void* d_out, int out_size) {
    const float* x       = (const float*)d_in[0];
    const float* ln_g    = (const float*)d_in[1];
    const float* ln_b    = (const float*)d_in[2];
    const float* W_in    = (const float*)d_in[3];
    const float* conv_w  = (const float*)d_in[4];
    const float* conv_b  = (const float*)d_in[5];
    const float* W_xproj = (const float*)d_in[6];
    const float* W_dt    = (const float*)d_in[7];
    const float* b_dt    = (const float*)d_in[8];
    const float* A_log   = (const float*)d_in[9];
    const float* D_skip  = (const float*)d_in[10];
    const float* W_out   = (const float*)d_in[11];
    float* out = (float*)d_out;

    __nv_bfloat16 *xn, *ubf, *dtbf, *yg, *wtin, *wtout, *wtxp, *wtdt;
    float *xz, *u, *part, *xdbl, *delta;
    cudaGetSymbolAddress((void**)&xn,    g_xn_bf);
    cudaGetSymbolAddress((void**)&xz,    g_xz);
    cudaGetSymbolAddress((void**)&u,     g_u);
    cudaGetSymbolAddress((void**)&ubf,   g_u_bf);
    cudaGetSymbolAddress((void**)&part,  g_part);
    cudaGetSymbolAddress((void**)&xdbl,  g_xdbl);
    cudaGetSymbolAddress((void**)&dtbf,  g_dt_bf);
    cudaGetSymbolAddress((void**)&delta, g_delta);
    cudaGetSymbolAddress((void**)&yg,    g_yg_bf);
    cudaGetSymbolAddress((void**)&wtin,  g_wt_in);
    cudaGetSymbolAddress((void**)&wtout, g_wt_out);
    cudaGetSymbolAddress((void**)&wtxp,  g_wt_xp);
    cudaGetSymbolAddress((void**)&wtdt,  g_wt_dt);

    const int smemBytes = 4 * 2 * 128 * 128;   // 131072
    cudaFuncSetAttribute(mma_gemm_kernel<0>, cudaFuncAttributeMaxDynamicSharedMemorySize, smemBytes);
    cudaFuncSetAttribute(mma_gemm_kernel<1>, cudaFuncAttributeMaxDynamicSharedMemorySize, smemBytes);
    cudaFuncSetAttribute(mma_gemm_kernel<2>, cudaFuncAttributeMaxDynamicSharedMemorySize, smemBytes);

    dim3 tb(32, 8);

    // 1) transpose W_in -> bf16 [4096,1024]
    transpose_bf_kernel<<<dim3(DM / 32, (2 * DI) / 32), tb>>>(W_in, wtin, DM, 2 * DI, 2 * DI);
    // 2) layernorm -> bf16
    ln_kernel<<<BL, 256>>>(x, ln_g, ln_b, xn);
    // 3) transpose W_out -> bf16 [1024,2048]
    transpose_bf_kernel<<<dim3(DI / 32, DM / 32), tb>>>(W_out, wtout, DI, DM, DM);
    // 4) xz = xn @ W_in  (PROFILED LAUNCH)
    mma_gemm_kernel<0><<<dim3((2 * DI) / 128, BL / 128, 1), 256, smemBytes>>>(
        xn, wtin, xz, BL, 2 * DI, DM, DM, 2 * DI, nullptr, DM, 0);
    // 5) conv + silu
    conv_silu_kernel<<<((size_t)BL * DI) / 256, 256>>>(xz, conv_w, conv_b, u, ubf);
    // 6,7) remaining weight transposes
    transpose_bf_kernel<<<dim3(DI / 32, GP / 32), tb>>>(W_xproj, wtxp, DI, GDIM, GP);
    transpose_bf_kernel<<<dim3(RANK / 32, DI / 32), tb>>>(W_dt, wtdt, RANK, DI, DI);
    // 8) x_dbl partials = u @ W_xproj (split-K 4)
    mma_gemm_kernel<0><<<dim3(GP / 128, BL / 128, SPLITK), 256, smemBytes>>>(
        ubf, wtxp, part, BL, GP, DI, DI, GP, nullptr, DI / SPLITK, (size_t)BL * GP);
    // 9) reduce partials -> xdbl fp32 + dt bf16
    reduce_xdbl_kernel<<<(BL * GP) / 256, 256>>>(part, xdbl, dtbf);
    // 10) delta = softplus(dt @ W_dt + b_dt)
    mma_gemm_kernel<1><<<dim3(DI / 128, BL / 128, 1), 256, smemBytes>>>(
        dtbf, wtdt, delta, BL, DI, RANK, RANK, DI, b_dt, RANK, 0);
    // 11) selective scan -> yg bf16
    scan_kernel<<<BATCH * (DI / 16), 256>>>(delta, u, xdbl, xz, A_log, D_skip, yg);
    // 12) out = x + yg @ W_out
    mma_gemm_kernel<2><<<dim3(DM / 128, BL / 128, 1), 256, smemBytes>>>(
        yg, wtout, out, BL, DM, DI, DI, DM, x, DI, 0);
}

// round 5
// speedup vs baseline: 9.2168x; 2.0867x over previous
#include <cuda_runtime.h>
#include <cuda_bf16.h>
#include <math.h>
#include <stdint.h>

// ---------------- problem constants ----------------
#define BATCH   2
#define LSEQ    2048
#define DM      1024
#define DI      2048
#define DS      16
#define DC      4
#define RANK    64
#define GDIM    96
#define GP      128
#define BL      (BATCH*LSEQ)  // 4096
#define SPLITK  4
#define NCH     8
#define CHL     (LSEQ/NCH)    // 256

// ---------------- scratch ----------------
__device__ __nv_bfloat16 g_xn_bf [(size_t)BL*DM];
__device__ float         g_xz    [(size_t)BL*2*DI];
__device__ float         g_u     [(size_t)BL*DI];
__device__ __nv_bfloat16 g_u_bf  [(size_t)BL*DI];
__device__ float         g_part  [(size_t)SPLITK*BL*GP];
__device__ float         g_xdbl  [(size_t)BL*GP];
__device__ __nv_bfloat16 g_dt_bf [(size_t)BL*RANK];
__device__ float         g_delta [(size_t)BL*DI];
__device__ __nv_bfloat16 g_yg_bf [(size_t)BL*DI];
__device__ float         g_S     [(size_t)BATCH*NCH*DI*DS];
__device__ float         g_H0    [(size_t)BATCH*NCH*DI*DS];
__device__ float         g_dsum  [(size_t)BATCH*NCH*DI];
__device__ __nv_bfloat16 g_wt_in [(size_t)(2*DI)*DM];
__device__ __nv_bfloat16 g_wt_out[(size_t)DM*DI];
__device__ __nv_bfloat16 g_wt_xp [(size_t)GP*DI];
__device__ __nv_bfloat16 g_wt_dt [(size_t)DI*RANK];

// ---------------- helpers ----------------
__device__ __forceinline__ uint32_t smem_u32(const void* p) {
    uint32_t a;
    asm("{ .reg .u64 t; cvta.to.shared.u64 t, %1; cvt.u32.u64 %0, t; }" : "=r"(a) : "l"(p));
    return a;
}
__device__ __forceinline__ void cp16(uint32_t dst, const void* src) {
    asm volatile("cp.async.cg.shared.global [%0], [%1], 16;" :: "r"(dst), "l"(src));
}
#define CP_COMMIT() asm volatile("cp.async.commit_group;")
#define CP_WAIT2()  asm volatile("cp.async.wait_group 2;")

__device__ __forceinline__ void mma_bf16(float* c, const uint32_t* a, const uint32_t* b) {
    asm volatile(
        "mma.sync.aligned.m16n8k16.row.col.f32.bf16.bf16.f32 "
        "{%0,%1,%2,%3}, {%4,%5,%6,%7}, {%8,%9}, {%0,%1,%2,%3};"
        : "+f"(c[0]), "+f"(c[1]), "+f"(c[2]), "+f"(c[3])
        : "r"(a[0]), "r"(a[1]), "r"(a[2]), "r"(a[3]), "r"(b[0]), "r"(b[1]));
}
__device__ __forceinline__ float softplus_f(float t) {
    return (t > 20.f) ? t : __logf(1.f + __expf(t));
}
// dA_n = w^(n+1), n=0..15, via log-depth multiply tree
__device__ __forceinline__ void powers16(float w, float* pw) {
    const float w2 = w * w, w4 = w2 * w2, w8 = w4 * w4;
    pw[0]  = w;        pw[1]  = w2;       pw[2]  = w2 * w;   pw[3]  = w4;
    pw[4]  = w4 * w;   pw[5]  = w4 * w2;  pw[6]  = w4 * pw[2]; pw[7] = w8;
    pw[8]  = w8 * w;   pw[9]  = w8 * w2;  pw[10] = w8 * pw[2]; pw[11] = w8 * w4;
    pw[12] = w8 * pw[4]; pw[13] = w8 * pw[5]; pw[14] = w8 * pw[6]; pw[15] = w8 * w8;
}

// ---------------- layernorm -> bf16 ----------------
__global__ void ln_kernel(const float* __restrict__ x,
                          const float* __restrict__ gamma,
                          const float* __restrict__ beta,
                          __nv_bfloat16* __restrict__ out) {
    __shared__ float rs[8], rq[8];
    const int row = blockIdx.x;
    const int tid = threadIdx.x;
    const float* xr = x + (size_t)row * DM;
    float v[4];
    float s = 0.f, s2 = 0.f;
#pragma unroll
    for (int i = 0; i < 4; i++) {
        v[i] = xr[tid + 256 * i];
        s  += v[i];
        s2 += v[i] * v[i];
    }
#pragma unroll
    for (int o = 16; o > 0; o >>= 1) {
        s  += __shfl_xor_sync(0xffffffffu, s,  o);
        s2 += __shfl_xor_sync(0xffffffffu, s2, o);
    }
    if ((tid & 31) == 0) { rs[tid >> 5] = s; rq[tid >> 5] = s2; }
    __syncthreads();
    s = 0.f; s2 = 0.f;
#pragma unroll
    for (int i = 0; i < 8; i++) { s += rs[i]; s2 += rq[i]; }
    const float mean = s * (1.f / DM);
    const float var  = s2 * (1.f / DM) - mean * mean;
    const float rstd = rsqrtf(var + 1e-5f);
    __nv_bfloat16* orow = out + (size_t)row * DM;
#pragma unroll
    for (int i = 0; i < 4; i++) {
        const int c = tid + 256 * i;
        orow[c] = __float2bfloat16((v[i] - mean) * rstd * gamma[c] + beta[c]);
    }
}

// ---------------- transpose fp32 -> bf16 ----------------
__global__ void transpose_bf_kernel(const float* __restrict__ in,
                                    __nv_bfloat16* __restrict__ out,
                                    int K, int Nsrc, int Nout) {
    __shared__ float t[32][33];
    const int kb = blockIdx.x * 32;
    const int nb = blockIdx.y * 32;
    const int tx = threadIdx.x, ty = threadIdx.y;
#pragma unroll
    for (int j = ty; j < 32; j += 8) {
        const int n = nb + tx;
        t[j][tx] = (n < Nsrc) ? in[(size_t)(kb + j) * Nsrc + n] : 0.f;
    }
    __syncthreads();
#pragma unroll
    for (int j = ty; j < 32; j += 8) {
        const int n = nb + j;
        if (n < Nout) out[(size_t)n * K + kb + tx] = __float2bfloat16(t[tx][j]);
    }
}

// ---------------- conv + silu ----------------
__global__ void conv_silu_kernel(const float* __restrict__ xz,
                                 const float* __restrict__ w,
                                 const float* __restrict__ bias,
                                 float* __restrict__ u,
                                 __nv_bfloat16* __restrict__ ubf) {
    const int idx = blockIdx.x * blockDim.x + threadIdx.x;
    const int d  = idx & (DI - 1);
    const int bl = idx >> 11;
    const int l  = bl & (LSEQ - 1);
    float acc = bias[d];
#pragma unroll
    for (int j = 0; j < DC; j++) {
        const int lj = l - (DC - 1) + j;
        if (lj >= 0)
            acc = fmaf(w[d * DC + j], xz[(size_t)(bl - (DC - 1) + j) * (2 * DI) + d], acc);
    }
    const float sig = 1.f / (1.f + __expf(-acc));
    const float r = acc * sig;
    u[idx]   = r;
    ubf[idx] = __float2bfloat16(r);
}

// ---------------- bf16 mma.sync GEMM (2 CTA/SM) ----------------
// C[M,N] = A[M,K] @ Bt[N,K]^T ; A,Bt bf16; C fp32.
// EPI: 0 none | 1 softplus(acc+E[col]) | 2 acc+E[r*ldc+c]
template <int EPI>
__global__ __launch_bounds__(256, 2)
void mma_gemm_kernel(const __nv_bfloat16* __restrict__ A,
                     const __nv_bfloat16* __restrict__ Bt,
                     float* __restrict__ C, int M, int N,
                     int lda, int ldb, int ldc, const float* __restrict__ E,
                     int Kloc, size_t partStride) {
    constexpr int BM = 128, BN = 128, BK = 32;
    constexpr int PITCH = 80;               // bytes/row (16B aligned, conflict-free)
    constexpr int STAGE = 256 * PITCH;      // 20480
    constexpr int BOFF  = 128 * PITCH;      // 10240

    extern __shared__ __align__(128) char smem[];
    const uint32_t smem_b = smem_u32(smem);

    const int tid  = threadIdx.x;
    const int wid  = tid >> 5;
    const int lane = tid & 31;
    const int g    = lane >> 2;
    const int t    = lane & 3;

    const int warpRow = wid & 1;
    const int warpCol = wid >> 1;
    const int rowBase = blockIdx.y * BM;
    const int colBase = blockIdx.x * BN;
    const int kbase   = blockIdx.z * Kloc;
    C += (size_t)blockIdx.z * partStride;

    float acc[4][4][4];
#pragma unroll
    for (int i = 0; i < 4; i++)
#pragma unroll
        for (int j = 0; j < 4; j++)
#pragma unroll
            for (int q = 0; q < 4; q++) acc[i][j][q] = 0.f;

    const int nchunk = Kloc / BK;

    const int unit = lane >> 3;     // 0..3 (16B unit within 64B row)
    const int rsub = lane & 7;

    auto load_stage = [&](int kc, int s) {
        if (kc < nchunk) {
            const uint32_t base = smem_b + (uint32_t)s * STAGE;
#pragma unroll
            for (int it = 0; it < 4; it++) {
                const int r = it * 64 + wid * 8 + rsub;     // 0..255
                const uint32_t dst = base + (uint32_t)r * PITCH + unit * 16;
                if (r < 128)
                    cp16(dst, A + (size_t)(rowBase + r) * lda + kbase + kc * BK + unit * 8);
                else
                    cp16(dst, Bt + (size_t)(colBase + r - 128) * ldb + kbase + kc * BK + unit * 8);
            }
        }
        CP_COMMIT();
    };

    load_stage(0, 0);
    load_stage(1, 1);
    load_stage(2, 2);

    for (int i = 0; i < nchunk; i++) {
        CP_WAIT2();
        __syncthreads();
        load_stage(i + 3, (i + 3) & 3);

        const char* st = smem + (i & 3) * STAGE;
        const char* pa = st + (warpRow * 64 + g) * PITCH + t * 4;
        const char* pb = st + BOFF + (warpCol * 32 + g) * PITCH + t * 4;

#pragma unroll
        for (int ks = 0; ks < 2; ks++) {
            uint32_t afr[4][4], bfr[4][2];
#pragma unroll
            for (int mt = 0; mt < 4; mt++) {
                const char* p0 = pa + mt * 16 * PITCH + ks * 32;
                afr[mt][0] = *(const uint32_t*)(p0);
                afr[mt][1] = *(const uint32_t*)(p0 + 8 * PITCH);
                afr[mt][2] = *(const uint32_t*)(p0 + 16);
                afr[mt][3] = *(const uint32_t*)(p0 + 8 * PITCH + 16);
            }
#pragma unroll
            for (int nt = 0; nt < 4; nt++) {
                const char* q0 = pb + nt * 8 * PITCH + ks * 32;
                bfr[nt][0] = *(const uint32_t*)(q0);
                bfr[nt][1] = *(const uint32_t*)(q0 + 16);
            }
#pragma unroll
            for (int mt = 0; mt < 4; mt++)
#pragma unroll
                for (int nt = 0; nt < 4; nt++)
                    mma_bf16(acc[mt][nt], afr[mt], bfr[nt]);
        }
        __syncthreads();
    }

    const int rW = rowBase + warpRow * 64;
    const int cW = colBase + warpCol * 32;
#pragma unroll
    for (int mt = 0; mt < 4; mt++) {
#pragma unroll
        for (int nt = 0; nt < 4; nt++) {
            const int r0 = rW + mt * 16 + g;
            const int r1 = r0 + 8;
            const int c0 = cW + nt * 8 + 2 * t;
            float v0 = acc[mt][nt][0], v1 = acc[mt][nt][1];
            float v2 = acc[mt][nt][2], v3 = acc[mt][nt][3];
            if (EPI == 1) {
                const float b0 = E[c0], b1 = E[c0 + 1];
                v0 = softplus_f(v0 + b0);
                v1 = softplus_f(v1 + b1);
                v2 = softplus_f(v2 + b0);
                v3 = softplus_f(v3 + b1);
            } else if (EPI == 2) {
                const float2 e0 = *(const float2*)(E + (size_t)r0 * ldc + c0);
                const float2 e1 = *(const float2*)(E + (size_t)r1 * ldc + c0);
                v0 += e0.x; v1 += e0.y; v2 += e1.x; v3 += e1.y;
            }
            *(float2*)(C + (size_t)r0 * ldc + c0) = make_float2(v0, v1);
            *(float2*)(C + (size_t)r1 * ldc + c0) = make_float2(v2, v3);
        }
    }
}

// ---------------- split-K reduce + dt->bf16 ----------------
__global__ void reduce_xdbl_kernel(const float* __restrict__ part,
                                   float* __restrict__ xdbl,
                                   __nv_bfloat16* __restrict__ dtbf) {
    const int idx = blockIdx.x * blockDim.x + threadIdx.x;
    const size_t S = (size_t)BL * GP;
    float s = part[idx] + part[idx + S] + part[idx + 2 * S] + part[idx + 3 * S];
    xdbl[idx] = s;
    const int col = idx & (GP - 1);
    if (col < RANK) dtbf[(size_t)(idx >> 7) * RANK + col] = __float2bfloat16(s);
}

// ---------------- scan pass A: per-chunk local scan -> (S, sum delta) ------
__global__ void scanA_kernel(const float* __restrict__ delta,
                             const float* __restrict__ u,
                             const float* __restrict__ xdbl,
                             const float* __restrict__ A_log,
                             float* __restrict__ S, float* __restrict__ dsum) {
    __shared__ float Bs[CHL * DS];
    const int tid = threadIdx.x;                 // 128
    const int d = blockIdx.x * 128 + tid;
    const int c = blockIdx.y, b = blockIdx.z;
    const int l0 = c * CHL;

    for (int i = tid; i < CHL * DS; i += 128) {
        const int l = i >> 4, n = i & 15;
        Bs[i] = xdbl[((size_t)(b * LSEQ + l0 + l)) * GP + RANK + n];
    }

    float Av[DS];
#pragma unroll
    for (int n = 0; n < DS; n++) Av[n] = -__expf(A_log[d * DS + n]);
    bool structured = (Av[0] < 0.f);
#pragma unroll
    for (int n = 1; n < DS; n++)
        structured = structured && (fabsf(Av[n] - (n + 1) * Av[0]) <= 1e-5f * fabsf(Av[n]));
    __syncthreads();

    float h[DS];
#pragma unroll
    for (int n = 0; n < DS; n++) h[n] = 0.f;
    float ds = 0.f;

    size_t p = ((size_t)(b * LSEQ + l0)) * DI + d;
    for (int l = 0; l < CHL; l++, p += DI) {
        const float dv = delta[p];
        const float uv = u[p];
        ds += dv;
        const float cv = dv * uv;
        float pw[DS];
        if (structured) {
            powers16(__expf(dv * Av[0]), pw);
        } else {
#pragma unroll
            for (int n = 0; n < DS; n++) pw[n] = __expf(dv * Av[n]);
        }
#pragma unroll
        for (int n = 0; n < DS; n++)
            h[n] = fmaf(pw[n], h[n], cv * Bs[l * DS + n]);
    }

    const size_t o = ((size_t)((b * NCH + c) * DI) + d) * DS;
#pragma unroll
    for (int n = 0; n < DS; n++) S[o + n] = h[n];
    dsum[(size_t)(b * NCH + c) * DI + d] = ds;
}

// ---------------- scan pass B: sequential chunk combine -> H0 ----------
__global__ void scanB_kernel(const float* __restrict__ S,
                             const float* __restrict__ dsum,
                             const float* __restrict__ A_log,
                             float* __restrict__ H0) {
    const int idx = blockIdx.x * blockDim.x + threadIdx.x;  // 65536
    const int n = idx & 15;
    const int d = (idx >> 4) & (DI - 1);
    const int b = idx >> 15;
    const float Av = -__expf(A_log[d * DS + n]);
    float h = 0.f;
#pragma unroll
    for (int c = 0; c < NCH; c++) {
        const size_t o = ((size_t)((b * NCH + c) * DI) + d) * DS + n;
        H0[o] = h;
        const float P = __expf(dsum[(size_t)(b * NCH + c) * DI + d] * Av);
        h = fmaf(P, h, S[o]);
    }
}

// ---------------- scan pass C: replay with h0, produce gated output --------
__global__ void scanC_kernel(const float* __restrict__ delta,
                             const float* __restrict__ u,
                             const float* __restrict__ xdbl,
                             const float* __restrict__ xz,
                             const float* __restrict__ A_log,
                             const float* __restrict__ Dskip,
                             const float* __restrict__ H0,
                             __nv_bfloat16* __restrict__ yg) {
    __shared__ float Bs[CHL * DS];
    __shared__ float Cs[CHL * DS];
    const int tid = threadIdx.x;
    const int d = blockIdx.x * 128 + tid;
    const int c = blockIdx.y, b = blockIdx.z;
    const int l0 = c * CHL;

    for (int i = tid; i < CHL * DS; i += 128) {
        const int l = i >> 4, n = i & 15;
        const size_t row = ((size_t)(b * LSEQ + l0 + l)) * GP + RANK;
        Bs[i] = xdbl[row + n];
        Cs[i] = xdbl[row + DS + n];
    }

    float Av[DS];
#pragma unroll
    for (int n = 0; n < DS; n++) Av[n] = -__expf(A_log[d * DS + n]);
    bool structured = (Av[0] < 0.f);
#pragma unroll
    for (int n = 1; n < DS; n++)
        structured = structured && (fabsf(Av[n] - (n + 1) * Av[0]) <= 1e-5f * fabsf(Av[n]));
    const float dsk = Dskip[d];
    __syncthreads();

    float h[DS];
    const size_t ho = ((size_t)((b * NCH + c) * DI) + d) * DS;
#pragma unroll
    for (int n = 0; n < DS; n++) h[n] = H0[ho + n];

    size_t p = ((size_t)(b * LSEQ + l0)) * DI + d;
    for (int l = 0; l < CHL; l++, p += DI) {
        const float dv = delta[p];
        const float uv = u[p];
        const float zv = xz[((size_t)(b * LSEQ + l0 + l)) * (2 * DI) + DI + d];
        const float cv = dv * uv;
        float pw[DS];
        if (structured) {
            powers16(__expf(dv * Av[0]), pw);
        } else {
#pragma unroll
            for (int n = 0; n < DS; n++) pw[n] = __expf(dv * Av[n]);
        }
        float y0 = 0.f, y1 = 0.f, y2 = 0.f, y3 = 0.f;
#pragma unroll
        for (int n = 0; n < DS; n += 4) {
            h[n]     = fmaf(pw[n],     h[n],     cv * Bs[l * DS + n]);
            h[n + 1] = fmaf(pw[n + 1], h[n + 1], cv * Bs[l * DS + n + 1]);
            h[n + 2] = fmaf(pw[n + 2], h[n + 2], cv * Bs[l * DS + n + 2]);
            h[n + 3] = fmaf(pw[n + 3], h[n + 3], cv * Bs[l * DS + n + 3]);
            y0 = fmaf(h[n],     Cs[l * DS + n],     y0);
            y1 = fmaf(h[n + 1], Cs[l * DS + n + 1], y1);
            y2 = fmaf(h[n + 2], Cs[l * DS + n + 2], y2);
            y3 = fmaf(h[n + 3], Cs[l * DS + n + 3], y3);
        }
        const float y = (y0 + y1) + (y2 + y3) + uv * dsk;
        const float sig = 1.f / (1.f + __expf(-zv));
        yg[p] = __float2bfloat16(y * (zv * sig));
    }
}

// ---------------- launch ----------------
extern "C" void kernel_launch(void* const* d_in, const int* in_sizes, int n_in,
                              void* d_out, int out_size) {
    const float* x       = (const float*)d_in[0];
    const float* ln_g    = (const float*)d_in[1];
    const float* ln_b    = (const float*)d_in[2];
    const float* W_in    = (const float*)d_in[3];
    const float* conv_w  = (const float*)d_in[4];
    const float* conv_b  = (const float*)d_in[5];
    const float* W_xproj = (const float*)d_in[6];
    const float* W_dt    = (const float*)d_in[7];
    const float* b_dt    = (const float*)d_in[8];
    const float* A_log   = (const float*)d_in[9];
    const float* D_skip  = (const float*)d_in[10];
    const float* W_out   = (const float*)d_in[11];
    float* out = (float*)d_out;

    __nv_bfloat16 *xn, *ubf, *dtbf, *yg, *wtin, *wtout, *wtxp, *wtdt;
    float *xz, *u, *part, *xdbl, *delta, *Sb, *H0b, *dsumb;
    cudaGetSymbolAddress((void**)&xn,    g_xn_bf);
    cudaGetSymbolAddress((void**)&xz,    g_xz);
    cudaGetSymbolAddress((void**)&u,     g_u);
    cudaGetSymbolAddress((void**)&ubf,   g_u_bf);
    cudaGetSymbolAddress((void**)&part,  g_part);
    cudaGetSymbolAddress((void**)&xdbl,  g_xdbl);
    cudaGetSymbolAddress((void**)&dtbf,  g_dt_bf);
    cudaGetSymbolAddress((void**)&delta, g_delta);
    cudaGetSymbolAddress((void**)&yg,    g_yg_bf);
    cudaGetSymbolAddress((void**)&Sb,    g_S);
    cudaGetSymbolAddress((void**)&H0b,   g_H0);
    cudaGetSymbolAddress((void**)&dsumb, g_dsum);
    cudaGetSymbolAddress((void**)&wtin,  g_wt_in);
    cudaGetSymbolAddress((void**)&wtout, g_wt_out);
    cudaGetSymbolAddress((void**)&wtxp,  g_wt_xp);
    cudaGetSymbolAddress((void**)&wtdt,  g_wt_dt);

    const int smemBytes = 4 * 256 * 80;   // 81920
    cudaFuncSetAttribute(mma_gemm_kernel<0>, cudaFuncAttributeMaxDynamicSharedMemorySize, smemBytes);
    cudaFuncSetAttribute(mma_gemm_kernel<1>, cudaFuncAttributeMaxDynamicSharedMemorySize, smemBytes);
    cudaFuncSetAttribute(mma_gemm_kernel<2>, cudaFuncAttributeMaxDynamicSharedMemorySize, smemBytes);

    dim3 tb(32, 8);

    // 1) transpose W_in
    transpose_bf_kernel<<<dim3(DM / 32, (2 * DI) / 32), tb>>>(W_in, wtin, DM, 2 * DI, 2 * DI);
    // 2) layernorm
    ln_kernel<<<BL, 256>>>(x, ln_g, ln_b, xn);
    // 3) transpose W_out
    transpose_bf_kernel<<<dim3(DI / 32, DM / 32), tb>>>(W_out, wtout, DI, DM, DM);
    // 4) xz = xn @ W_in  (PROFILED)
    mma_gemm_kernel<0><<<dim3((2 * DI) / 128, BL / 128, 1), 256, smemBytes>>>(
        xn, wtin, xz, BL, 2 * DI, DM, DM, 2 * DI, nullptr, DM, 0);
    // 5) conv + silu
    conv_silu_kernel<<<((size_t)BL * DI) / 256, 256>>>(xz, conv_w, conv_b, u, ubf);
    // 6,7) remaining transposes
    transpose_bf_kernel<<<dim3(DI / 32, GP / 32), tb>>>(W_xproj, wtxp, DI, GDIM, GP);
    transpose_bf_kernel<<<dim3(RANK / 32, DI / 32), tb>>>(W_dt, wtdt, RANK, DI, DI);
    // 8) x_dbl partials (split-K)
    mma_gemm_kernel<0><<<dim3(GP / 128, BL / 128, SPLITK), 256, smemBytes>>>(
        ubf, wtxp, part, BL, GP, DI, DI, GP, nullptr, DI / SPLITK, (size_t)BL * GP);
    // 9) reduce
    reduce_xdbl_kernel<<<(BL * GP) / 256, 256>>>(part, xdbl, dtbf);
    // 10) delta
    mma_gemm_kernel<1><<<dim3(DI / 128, BL / 128, 1), 256, smemBytes>>>(
        dtbf, wtdt, delta, BL, DI, RANK, RANK, DI, b_dt, RANK, 0);
    // 11-13) chunked selective scan
    scanA_kernel<<<dim3(DI / 128, NCH, BATCH), 128>>>(delta, u, xdbl, A_log, Sb, dsumb);
    scanB_kernel<<<(BATCH * DI * DS) / 256, 256>>>(Sb, dsumb, A_log, H0b);
    scanC_kernel<<<dim3(DI / 128, NCH, BATCH), 128>>>(delta, u, xdbl, xz, A_log, D_skip, H0b, yg);
    // 14) out = x + yg @ W_out
    mma_gemm_kernel<2><<<dim3(DM / 128, BL / 128, 1), 256, smemBytes>>>(
        yg, wtout, out, BL, DM, DI, DI, DM, x, DI, 0);
}

// round 6
// speedup vs baseline: 10.2673x; 1.1140x over previous
#include <cuda_runtime.h>
#include <cuda_bf16.h>
#include <math.h>
#include <stdint.h>

// ---------------- problem constants ----------------
#define BATCH   2
#define LSEQ    2048
#define DM      1024
#define DI      2048
#define DS      16
#define DC      4
#define RANK    64
#define GDIM    96
#define GP      128
#define BL      (BATCH*LSEQ)  // 4096
#define SPLITK  4
#define NCH     8
#define CHL     (LSEQ/NCH)    // 256

// ---------------- scratch ----------------
__device__ __nv_bfloat16 g_xn_bf [(size_t)BL*DM];
__device__ float         g_xz    [(size_t)BL*2*DI];
__device__ float         g_u     [(size_t)BL*DI];
__device__ __nv_bfloat16 g_u_bf  [(size_t)BL*DI];
__device__ float         g_part  [(size_t)SPLITK*BL*GP];
__device__ float         g_xdbl  [(size_t)BL*GP];
__device__ __nv_bfloat16 g_dt_bf [(size_t)BL*RANK];
__device__ float         g_delta [(size_t)BL*DI];
__device__ __nv_bfloat16 g_yg_bf [(size_t)BL*DI];
__device__ float         g_S     [(size_t)BATCH*NCH*DI*DS];
__device__ float         g_H0    [(size_t)BATCH*NCH*DI*DS];
__device__ float         g_dsum  [(size_t)BATCH*NCH*DI];
__device__ __nv_bfloat16 g_wt_in [(size_t)(2*DI)*DM];
__device__ __nv_bfloat16 g_wt_out[(size_t)DM*DI];
__device__ __nv_bfloat16 g_wt_xp [(size_t)GP*DI];
__device__ __nv_bfloat16 g_wt_dt [(size_t)DI*RANK];

// ---------------- helpers ----------------
__device__ __forceinline__ uint32_t smem_u32(const void* p) {
    uint32_t a;
    asm("{ .reg .u64 t; cvta.to.shared.u64 t, %1; cvt.u32.u64 %0, t; }" : "=r"(a) : "l"(p));
    return a;
}
__device__ __forceinline__ void cp16(uint32_t dst, const void* src) {
    asm volatile("cp.async.cg.shared.global [%0], [%1], 16;" :: "r"(dst), "l"(src));
}
#define CP_COMMIT() asm volatile("cp.async.commit_group;")
#define CP_WAIT1()  asm volatile("cp.async.wait_group 1;")

__device__ __forceinline__ void mma_bf16(float* c, const uint32_t* a, const uint32_t* b) {
    asm volatile(
        "mma.sync.aligned.m16n8k16.row.col.f32.bf16.bf16.f32 "
        "{%0,%1,%2,%3}, {%4,%5,%6,%7}, {%8,%9}, {%0,%1,%2,%3};"
        : "+f"(c[0]), "+f"(c[1]), "+f"(c[2]), "+f"(c[3])
        : "r"(a[0]), "r"(a[1]), "r"(a[2]), "r"(a[3]), "r"(b[0]), "r"(b[1]));
}
__device__ __forceinline__ float softplus_f(float t) {
    return (t > 20.f) ? t : __logf(1.f + __expf(t));
}
__device__ __forceinline__ void powers16(float w, float* pw) {
    const float w2 = w * w, w4 = w2 * w2, w8 = w4 * w4;
    pw[0]  = w;        pw[1]  = w2;       pw[2]  = w2 * w;   pw[3]  = w4;
    pw[4]  = w4 * w;   pw[5]  = w4 * w2;  pw[6]  = w4 * pw[2]; pw[7] = w8;
    pw[8]  = w8 * w;   pw[9]  = w8 * w2;  pw[10] = w8 * pw[2]; pw[11] = w8 * w4;
    pw[12] = w8 * pw[4]; pw[13] = w8 * pw[5]; pw[14] = w8 * pw[6]; pw[15] = w8 * w8;
}

// ---------------- layernorm -> bf16 ----------------
__global__ void ln_kernel(const float* __restrict__ x,
                          const float* __restrict__ gamma,
                          const float* __restrict__ beta,
                          __nv_bfloat16* __restrict__ out) {
    __shared__ float rs[8], rq[8];
    const int row = blockIdx.x;
    const int tid = threadIdx.x;
    const float* xr = x + (size_t)row * DM;
    float v[4];
    float s = 0.f, s2 = 0.f;
#pragma unroll
    for (int i = 0; i < 4; i++) {
        v[i] = xr[tid + 256 * i];
        s  += v[i];
        s2 += v[i] * v[i];
    }
#pragma unroll
    for (int o = 16; o > 0; o >>= 1) {
        s  += __shfl_xor_sync(0xffffffffu, s,  o);
        s2 += __shfl_xor_sync(0xffffffffu, s2, o);
    }
    if ((tid & 31) == 0) { rs[tid >> 5] = s; rq[tid >> 5] = s2; }
    __syncthreads();
    s = 0.f; s2 = 0.f;
#pragma unroll
    for (int i = 0; i < 8; i++) { s += rs[i]; s2 += rq[i]; }
    const float mean = s * (1.f / DM);
    const float var  = s2 * (1.f / DM) - mean * mean;
    const float rstd = rsqrtf(var + 1e-5f);
    __nv_bfloat16* orow = out + (size_t)row * DM;
#pragma unroll
    for (int i = 0; i < 4; i++) {
        const int c = tid + 256 * i;
        orow[c] = __float2bfloat16((v[i] - mean) * rstd * gamma[c] + beta[c]);
    }
}

// ---------------- transpose fp32 -> bf16 ----------------
__global__ void transpose_bf_kernel(const float* __restrict__ in,
                                    __nv_bfloat16* __restrict__ out,
                                    int K, int Nsrc, int Nout) {
    __shared__ float t[32][33];
    const int kb = blockIdx.x * 32;
    const int nb = blockIdx.y * 32;
    const int tx = threadIdx.x, ty = threadIdx.y;
#pragma unroll
    for (int j = ty; j < 32; j += 8) {
        const int n = nb + tx;
        t[j][tx] = (n < Nsrc) ? in[(size_t)(kb + j) * Nsrc + n] : 0.f;
    }
    __syncthreads();
#pragma unroll
    for (int j = ty; j < 32; j += 8) {
        const int n = nb + j;
        if (n < Nout) out[(size_t)n * K + kb + tx] = __float2bfloat16(t[tx][j]);
    }
}

// ---------------- conv + silu ----------------
__global__ void conv_silu_kernel(const float* __restrict__ xz,
                                 const float* __restrict__ w,
                                 const float* __restrict__ bias,
                                 float* __restrict__ u,
                                 __nv_bfloat16* __restrict__ ubf) {
    const int idx = blockIdx.x * blockDim.x + threadIdx.x;
    const int d  = idx & (DI - 1);
    const int bl = idx >> 11;
    const int l  = bl & (LSEQ - 1);
    float acc = bias[d];
#pragma unroll
    for (int j = 0; j < DC; j++) {
        const int lj = l - (DC - 1) + j;
        if (lj >= 0)
            acc = fmaf(w[d * DC + j], xz[(size_t)(bl - (DC - 1) + j) * (2 * DI) + d], acc);
    }
    const float sig = 1.f / (1.f + __expf(-acc));
    const float r = acc * sig;
    u[idx]   = r;
    ubf[idx] = __float2bfloat16(r);
}

// ---------------- bf16 mma.sync GEMM: BK=64, 3 stages, 1 sync/iter, 2 CTA/SM
// C[M,N] = A[M,K] @ Bt[N,K]^T ; A,Bt bf16; C fp32.
// EPI: 0 none | 1 softplus(acc+E[col]) | 2 acc+E[r*ldc+c]
template <int EPI>
__global__ __launch_bounds__(256, 2)
void mma_gemm_kernel(const __nv_bfloat16* __restrict__ A,
                     const __nv_bfloat16* __restrict__ Bt,
                     float* __restrict__ C, int M, int N,
                     int lda, int ldb, int ldc, const float* __restrict__ E,
                     int Kloc, size_t partStride) {
    constexpr int BM = 128, BN = 128, BK = 64;
    constexpr int STAGE_BYTES = 2 * 128 * 128;   // A 16KB + B 16KB
    constexpr int STAGES = 3;

    extern __shared__ __align__(128) char smem[];
    const uint32_t smem_b = smem_u32(smem);

    const int tid  = threadIdx.x;
    const int wid  = tid >> 5;
    const int lane = tid & 31;
    const int g    = lane >> 2;
    const int t    = lane & 3;

    const int warpRow = wid & 1;
    const int warpCol = wid >> 1;
    const int rowBase = blockIdx.y * BM;
    const int colBase = blockIdx.x * BN;
    const int kbase   = blockIdx.z * Kloc;
    C += (size_t)blockIdx.z * partStride;

    float acc[4][4][4];
#pragma unroll
    for (int i = 0; i < 4; i++)
#pragma unroll
        for (int j = 0; j < 4; j++)
#pragma unroll
            for (int q = 0; q < 4; q++) acc[i][j][q] = 0.f;

    const int nchunk = Kloc / BK;

    // loader: XOR-swizzled 128B rows; per warp 4 rows per 32-row group
    auto load_stage = [&](int kc, int s) {
        if (kc < nchunk) {
            const uint32_t base = smem_b + (uint32_t)s * STAGE_BYTES;
            const int rw = wid * 4 + (lane >> 3);
            const int un = lane & 7;
#pragma unroll
            for (int it = 0; it < 4; it++) {
                const int r = it * 32 + rw;
                const uint32_t sw = (uint32_t)((un ^ (r & 7)) << 4);
                cp16(base + (uint32_t)r * 128 + sw,
                     A + (size_t)(rowBase + r) * lda + kbase + kc * BK + un * 8);
                cp16(base + 16384u + (uint32_t)r * 128 + sw,
                     Bt + (size_t)(colBase + r) * ldb + kbase + kc * BK + un * 8);
            }
        }
        CP_COMMIT();
    };

    load_stage(0, 0);
    load_stage(1, 1);

    int sidx = 0;
    for (int i = 0; i < nchunk; i++) {
        CP_WAIT1();
        __syncthreads();           // single barrier per iteration
        int snext = sidx + 2; if (snext >= STAGES) snext -= STAGES;
        load_stage(i + 2, snext);

        const char* st = smem + sidx * STAGE_BYTES;
        const char* pa = st + ((warpRow * 64 + g) * 128) + 4 * t;
        const char* pb = st + 16384 + ((warpCol * 32 + g) * 128) + 4 * t;

#pragma unroll
        for (int ks = 0; ks < 4; ks++) {
            const int ku = ks * 2;
            uint32_t afr[4][4], bfr[4][2];
#pragma unroll
            for (int mt = 0; mt < 4; mt++) {
                const char* p0 = pa + (mt * 16) * 128;
                afr[mt][0] = *(const uint32_t*)(p0 + (((ku)     ^ g) << 4));
                afr[mt][1] = *(const uint32_t*)(p0 + 8 * 128 + (((ku)     ^ g) << 4));
                afr[mt][2] = *(const uint32_t*)(p0 + (((ku + 1) ^ g) << 4));
                afr[mt][3] = *(const uint32_t*)(p0 + 8 * 128 + (((ku + 1) ^ g) << 4));
            }
#pragma unroll
            for (int nt = 0; nt < 4; nt++) {
                const char* p0 = pb + (nt * 8) * 128;
                bfr[nt][0] = *(const uint32_t*)(p0 + (((ku)     ^ g) << 4));
                bfr[nt][1] = *(const uint32_t*)(p0 + (((ku + 1) ^ g) << 4));
            }
#pragma unroll
            for (int mt = 0; mt < 4; mt++)
#pragma unroll
                for (int nt = 0; nt < 4; nt++)
                    mma_bf16(acc[mt][nt], afr[mt], bfr[nt]);
        }
        sidx++; if (sidx >= STAGES) sidx -= STAGES;
    }

    // ---------------- epilogue ----------------
    const int rW = rowBase + warpRow * 64;
    const int cW = colBase + warpCol * 32;
#pragma unroll
    for (int mt = 0; mt < 4; mt++) {
#pragma unroll
        for (int nt = 0; nt < 4; nt++) {
            const int r0 = rW + mt * 16 + g;
            const int r1 = r0 + 8;
            const int c0 = cW + nt * 8 + 2 * t;
            float v0 = acc[mt][nt][0], v1 = acc[mt][nt][1];
            float v2 = acc[mt][nt][2], v3 = acc[mt][nt][3];
            if (EPI == 1) {
                const float b0 = E[c0], b1 = E[c0 + 1];
                v0 = softplus_f(v0 + b0);
                v1 = softplus_f(v1 + b1);
                v2 = softplus_f(v2 + b0);
                v3 = softplus_f(v3 + b1);
            } else if (EPI == 2) {
                const float2 e0 = *(const float2*)(E + (size_t)r0 * ldc + c0);
                const float2 e1 = *(const float2*)(E + (size_t)r1 * ldc + c0);
                v0 += e0.x; v1 += e0.y; v2 += e1.x; v3 += e1.y;
            }
            *(float2*)(C + (size_t)r0 * ldc + c0) = make_float2(v0, v1);
            *(float2*)(C + (size_t)r1 * ldc + c0) = make_float2(v2, v3);
        }
    }
}

// ---------------- split-K reduce + dt->bf16 ----------------
__global__ void reduce_xdbl_kernel(const float* __restrict__ part,
                                   float* __restrict__ xdbl,
                                   __nv_bfloat16* __restrict__ dtbf) {
    const int idx = blockIdx.x * blockDim.x + threadIdx.x;
    const size_t S = (size_t)BL * GP;
    float s = part[idx] + part[idx + S] + part[idx + 2 * S] + part[idx + 3 * S];
    xdbl[idx] = s;
    const int col = idx & (GP - 1);
    if (col < RANK) dtbf[(size_t)(idx >> 7) * RANK + col] = __float2bfloat16(s);
}

// ---------------- scan pass A ----------------
__global__ void scanA_kernel(const float* __restrict__ delta,
                             const float* __restrict__ u,
                             const float* __restrict__ xdbl,
                             const float* __restrict__ A_log,
                             float* __restrict__ S, float* __restrict__ dsum) {
    __shared__ float Bs[CHL * DS];
    const int tid = threadIdx.x;
    const int d = blockIdx.x * 128 + tid;
    const int c = blockIdx.y, b = blockIdx.z;
    const int l0 = c * CHL;

    for (int i = tid; i < CHL * DS; i += 128) {
        const int l = i >> 4, n = i & 15;
        Bs[i] = xdbl[((size_t)(b * LSEQ + l0 + l)) * GP + RANK + n];
    }

    float Av[DS];
#pragma unroll
    for (int n = 0; n < DS; n++) Av[n] = -__expf(A_log[d * DS + n]);
    bool structured = (Av[0] < 0.f);
#pragma unroll
    for (int n = 1; n < DS; n++)
        structured = structured && (fabsf(Av[n] - (n + 1) * Av[0]) <= 1e-5f * fabsf(Av[n]));
    __syncthreads();

    float h[DS];
#pragma unroll
    for (int n = 0; n < DS; n++) h[n] = 0.f;
    float ds = 0.f;

    size_t p = ((size_t)(b * LSEQ + l0)) * DI + d;
    for (int l = 0; l < CHL; l++, p += DI) {
        const float dv = delta[p];
        const float uv = u[p];
        ds += dv;
        const float cv = dv * uv;
        float pw[DS];
        if (structured) {
            powers16(__expf(dv * Av[0]), pw);
        } else {
#pragma unroll
            for (int n = 0; n < DS; n++) pw[n] = __expf(dv * Av[n]);
        }
#pragma unroll
        for (int n = 0; n < DS; n++)
            h[n] = fmaf(pw[n], h[n], cv * Bs[l * DS + n]);
    }

    const size_t o = ((size_t)((b * NCH + c) * DI) + d) * DS;
#pragma unroll
    for (int n = 0; n < DS; n++) S[o + n] = h[n];
    dsum[(size_t)(b * NCH + c) * DI + d] = ds;
}

// ---------------- scan pass B ----------------
__global__ void scanB_kernel(const float* __restrict__ S,
                             const float* __restrict__ dsum,
                             const float* __restrict__ A_log,
                             float* __restrict__ H0) {
    const int idx = blockIdx.x * blockDim.x + threadIdx.x;
    const int n = idx & 15;
    const int d = (idx >> 4) & (DI - 1);
    const int b = idx >> 15;
    const float Av = -__expf(A_log[d * DS + n]);
    float h = 0.f;
#pragma unroll
    for (int c = 0; c < NCH; c++) {
        const size_t o = ((size_t)((b * NCH + c) * DI) + d) * DS + n;
        H0[o] = h;
        const float P = __expf(dsum[(size_t)(b * NCH + c) * DI + d] * Av);
        h = fmaf(P, h, S[o]);
    }
}

// ---------------- scan pass C ----------------
__global__ void scanC_kernel(const float* __restrict__ delta,
                             const float* __restrict__ u,
                             const float* __restrict__ xdbl,
                             const float* __restrict__ xz,
                             const float* __restrict__ A_log,
                             const float* __restrict__ Dskip,
                             const float* __restrict__ H0,
                             __nv_bfloat16* __restrict__ yg) {
    __shared__ float Bs[CHL * DS];
    __shared__ float Cs[CHL * DS];
    const int tid = threadIdx.x;
    const int d = blockIdx.x * 128 + tid;
    const int c = blockIdx.y, b = blockIdx.z;
    const int l0 = c * CHL;

    for (int i = tid; i < CHL * DS; i += 128) {
        const int l = i >> 4, n = i & 15;
        const size_t row = ((size_t)(b * LSEQ + l0 + l)) * GP + RANK;
        Bs[i] = xdbl[row + n];
        Cs[i] = xdbl[row + DS + n];
    }

    float Av[DS];
#pragma unroll
    for (int n = 0; n < DS; n++) Av[n] = -__expf(A_log[d * DS + n]);
    bool structured = (Av[0] < 0.f);
#pragma unroll
    for (int n = 1; n < DS; n++)
        structured = structured && (fabsf(Av[n] - (n + 1) * Av[0]) <= 1e-5f * fabsf(Av[n]));
    const float dsk = Dskip[d];
    __syncthreads();

    float h[DS];
    const size_t ho = ((size_t)((b * NCH + c) * DI) + d) * DS;
#pragma unroll
    for (int n = 0; n < DS; n++) h[n] = H0[ho + n];

    size_t p = ((size_t)(b * LSEQ + l0)) * DI + d;
    for (int l = 0; l < CHL; l++, p += DI) {
        const float dv = delta[p];
        const float uv = u[p];
        const float zv = xz[((size_t)(b * LSEQ + l0 + l)) * (2 * DI) + DI + d];
        const float cv = dv * uv;
        float pw[DS];
        if (structured) {
            powers16(__expf(dv * Av[0]), pw);
        } else {
#pragma unroll
            for (int n = 0; n < DS; n++) pw[n] = __expf(dv * Av[n]);
        }
        float y0 = 0.f, y1 = 0.f, y2 = 0.f, y3 = 0.f;
#pragma unroll
        for (int n = 0; n < DS; n += 4) {
            h[n]     = fmaf(pw[n],     h[n],     cv * Bs[l * DS + n]);
            h[n + 1] = fmaf(pw[n + 1], h[n + 1], cv * Bs[l * DS + n + 1]);
            h[n + 2] = fmaf(pw[n + 2], h[n + 2], cv * Bs[l * DS + n + 2]);
            h[n + 3] = fmaf(pw[n + 3], h[n + 3], cv * Bs[l * DS + n + 3]);
            y0 = fmaf(h[n],     Cs[l * DS + n],     y0);
            y1 = fmaf(h[n + 1], Cs[l * DS + n + 1], y1);
            y2 = fmaf(h[n + 2], Cs[l * DS + n + 2], y2);
            y3 = fmaf(h[n + 3], Cs[l * DS + n + 3], y3);
        }
        const float y = (y0 + y1) + (y2 + y3) + uv * dsk;
        const float sig = 1.f / (1.f + __expf(-zv));
        yg[p] = __float2bfloat16(y * (zv * sig));
    }
}

// ---------------- launch ----------------
extern "C" void kernel_launch(void* const* d_in, const int* in_sizes, int n_in,
                              void* d_out, int out_size) {
    const float* x       = (const float*)d_in[0];
    const float* ln_g    = (const float*)d_in[1];
    const float* ln_b    = (const float*)d_in[2];
    const float* W_in    = (const float*)d_in[3];
    const float* conv_w  = (const float*)d_in[4];
    const float* conv_b  = (const float*)d_in[5];
    const float* W_xproj = (const float*)d_in[6];
    const float* W_dt    = (const float*)d_in[7];
    const float* b_dt    = (const float*)d_in[8];
    const float* A_log   = (const float*)d_in[9];
    const float* D_skip  = (const float*)d_in[10];
    const float* W_out   = (const float*)d_in[11];
    float* out = (float*)d_out;

    __nv_bfloat16 *xn, *ubf, *dtbf, *yg, *wtin, *wtout, *wtxp, *wtdt;
    float *xz, *u, *part, *xdbl, *delta, *Sb, *H0b, *dsumb;
    cudaGetSymbolAddress((void**)&xn,    g_xn_bf);
    cudaGetSymbolAddress((void**)&xz,    g_xz);
    cudaGetSymbolAddress((void**)&u,     g_u);
    cudaGetSymbolAddress((void**)&ubf,   g_u_bf);
    cudaGetSymbolAddress((void**)&part,  g_part);
    cudaGetSymbolAddress((void**)&xdbl,  g_xdbl);
    cudaGetSymbolAddress((void**)&dtbf,  g_dt_bf);
    cudaGetSymbolAddress((void**)&delta, g_delta);
    cudaGetSymbolAddress((void**)&yg,    g_yg_bf);
    cudaGetSymbolAddress((void**)&Sb,    g_S);
    cudaGetSymbolAddress((void**)&H0b,   g_H0);
    cudaGetSymbolAddress((void**)&dsumb, g_dsum);
    cudaGetSymbolAddress((void**)&wtin,  g_wt_in);
    cudaGetSymbolAddress((void**)&wtout, g_wt_out);
    cudaGetSymbolAddress((void**)&wtxp,  g_wt_xp);
    cudaGetSymbolAddress((void**)&wtdt,  g_wt_dt);

    const int smemBytes = 3 * 2 * 128 * 128;   // 98304
    cudaFuncSetAttribute(mma_gemm_kernel<0>, cudaFuncAttributeMaxDynamicSharedMemorySize, smemBytes);
    cudaFuncSetAttribute(mma_gemm_kernel<1>, cudaFuncAttributeMaxDynamicSharedMemorySize, smemBytes);
    cudaFuncSetAttribute(mma_gemm_kernel<2>, cudaFuncAttributeMaxDynamicSharedMemorySize, smemBytes);

    dim3 tb(32, 8);

    // 1) transpose W_in
    transpose_bf_kernel<<<dim3(DM / 32, (2 * DI) / 32), tb>>>(W_in, wtin, DM, 2 * DI, 2 * DI);
    // 2) layernorm
    ln_kernel<<<BL, 256>>>(x, ln_g, ln_b, xn);
    // 3) transpose W_out
    transpose_bf_kernel<<<dim3(DI / 32, DM / 32), tb>>>(W_out, wtout, DI, DM, DM);
    // 4) xz = xn @ W_in  (PROFILED)
    mma_gemm_kernel<0><<<dim3((2 * DI) / 128, BL / 128, 1), 256, smemBytes>>>(
        xn, wtin, xz, BL, 2 * DI, DM, DM, 2 * DI, nullptr, DM, 0);
    // 5) conv + silu
    conv_silu_kernel<<<((size_t)BL * DI) / 256, 256>>>(xz, conv_w, conv_b, u, ubf);
    // 6,7) remaining transposes
    transpose_bf_kernel<<<dim3(DI / 32, GP / 32), tb>>>(W_xproj, wtxp, DI, GDIM, GP);
    transpose_bf_kernel<<<dim3(RANK / 32, DI / 32), tb>>>(W_dt, wtdt, RANK, DI, DI);
    // 8) x_dbl partials (split-K)
    mma_gemm_kernel<0><<<dim3(GP / 128, BL / 128, SPLITK), 256, smemBytes>>>(
        ubf, wtxp, part, BL, GP, DI, DI, GP, nullptr, DI / SPLITK, (size_t)BL * GP);
    // 9) reduce
    reduce_xdbl_kernel<<<(BL * GP) / 256, 256>>>(part, xdbl, dtbf);
    // 10) delta
    mma_gemm_kernel<1><<<dim3(DI / 128, BL / 128, 1), 256, smemBytes>>>(
        dtbf, wtdt, delta, BL, DI, RANK, RANK, DI, b_dt, RANK, 0);
    // 11-13) chunked selective scan
    scanA_kernel<<<dim3(DI / 128, NCH, BATCH), 128>>>(delta, u, xdbl, A_log, Sb, dsumb);
    scanB_kernel<<<(BATCH * DI * DS) / 256, 256>>>(Sb, dsumb, A_log, H0b);
    scanC_kernel<<<dim3(DI / 128, NCH, BATCH), 128>>>(delta, u, xdbl, xz, A_log, D_skip, H0b, yg);
    // 14) out = x + yg @ W_out
    mma_gemm_kernel<2><<<dim3(DM / 128, BL / 128, 1), 256, smemBytes>>>(
        yg, wtout, out, BL, DM, DI, DI, DM, x, DI, 0);
}

// round 7
// speedup vs baseline: 11.6527x; 1.1349x over previous
#include <cuda_runtime.h>
#include <cuda_bf16.h>
#include <math.h>
#include <stdint.h>

// ---------------- problem constants ----------------
#define BATCH   2
#define LSEQ    2048
#define DM      1024
#define DI      2048
#define DS      16
#define DC      4
#define RANK    64
#define GDIM    96
#define GP      128
#define BL      (BATCH*LSEQ)  // 4096
#define SPLITK  4
#define NCH     8
#define CHL     (LSEQ/NCH)    // 256

// ---------------- scratch ----------------
__device__ __nv_bfloat16 g_xn_bf [(size_t)BL*DM];
__device__ __nv_bfloat16 g_xz_bf [(size_t)BL*2*DI];
__device__ __nv_bfloat16 g_u_bf  [(size_t)BL*DI];
__device__ float         g_part  [(size_t)SPLITK*BL*GP];
__device__ float         g_xdbl  [(size_t)BL*GP];
__device__ __nv_bfloat16 g_dt_bf [(size_t)BL*RANK];
__device__ float         g_delta [(size_t)BL*DI];
__device__ __nv_bfloat16 g_yg_bf [(size_t)BL*DI];
__device__ float         g_S     [(size_t)BATCH*NCH*DI*DS];
__device__ float         g_H0    [(size_t)BATCH*NCH*DI*DS];
__device__ float         g_dsum  [(size_t)BATCH*NCH*DI];
__device__ __nv_bfloat16 g_wt_in [(size_t)(2*DI)*DM];
__device__ __nv_bfloat16 g_wt_out[(size_t)DM*DI];
__device__ __nv_bfloat16 g_wt_xp [(size_t)GP*DI];
__device__ __nv_bfloat16 g_wt_dt [(size_t)DI*RANK];

// ---------------- helpers ----------------
__device__ __forceinline__ uint32_t smem_u32(const void* p) {
    uint32_t a;
    asm("{ .reg .u64 t; cvta.to.shared.u64 t, %1; cvt.u32.u64 %0, t; }" : "=r"(a) : "l"(p));
    return a;
}
__device__ __forceinline__ void cp16(uint32_t dst, const void* src) {
    asm volatile("cp.async.cg.shared.global [%0], [%1], 16;" :: "r"(dst), "l"(src));
}
#define CP_COMMIT() asm volatile("cp.async.commit_group;")
#define CP_WAIT1()  asm volatile("cp.async.wait_group 1;")

__device__ __forceinline__ void mma_bf16(float* c, const uint32_t* a, const uint32_t* b) {
    asm volatile(
        "mma.sync.aligned.m16n8k16.row.col.f32.bf16.bf16.f32 "
        "{%0,%1,%2,%3}, {%4,%5,%6,%7}, {%8,%9}, {%0,%1,%2,%3};"
        : "+f"(c[0]), "+f"(c[1]), "+f"(c[2]), "+f"(c[3])
        : "r"(a[0]), "r"(a[1]), "r"(a[2]), "r"(a[3]), "r"(b[0]), "r"(b[1]));
}
#define LDSM4(r0, r1, r2, r3, addr) \
    asm volatile("ldmatrix.sync.aligned.m8n8.x4.shared.b16 {%0,%1,%2,%3}, [%4];" \
        : "=r"(r0), "=r"(r1), "=r"(r2), "=r"(r3) : "r"(addr))

__device__ __forceinline__ float softplus_f(float t) {
    return (t > 20.f) ? t : __logf(1.f + __expf(t));
}
__device__ __forceinline__ void powers16(float w, float* pw) {
    const float w2 = w * w, w4 = w2 * w2, w8 = w4 * w4;
    pw[0]  = w;        pw[1]  = w2;       pw[2]  = w2 * w;   pw[3]  = w4;
    pw[4]  = w4 * w;   pw[5]  = w4 * w2;  pw[6]  = w4 * pw[2]; pw[7] = w8;
    pw[8]  = w8 * w;   pw[9]  = w8 * w2;  pw[10] = w8 * pw[2]; pw[11] = w8 * w4;
    pw[12] = w8 * pw[4]; pw[13] = w8 * pw[5]; pw[14] = w8 * pw[6]; pw[15] = w8 * w8;
}

// ---------------- layernorm -> bf16 ----------------
__global__ void ln_kernel(const float* __restrict__ x,
                          const float* __restrict__ gamma,
                          const float* __restrict__ beta,
                          __nv_bfloat16* __restrict__ out) {
    __shared__ float rs[8], rq[8];
    const int row = blockIdx.x;
    const int tid = threadIdx.x;
    const float* xr = x + (size_t)row * DM;
    float v[4];
    float s = 0.f, s2 = 0.f;
#pragma unroll
    for (int i = 0; i < 4; i++) {
        v[i] = xr[tid + 256 * i];
        s  += v[i];
        s2 += v[i] * v[i];
    }
#pragma unroll
    for (int o = 16; o > 0; o >>= 1) {
        s  += __shfl_xor_sync(0xffffffffu, s,  o);
        s2 += __shfl_xor_sync(0xffffffffu, s2, o);
    }
    if ((tid & 31) == 0) { rs[tid >> 5] = s; rq[tid >> 5] = s2; }
    __syncthreads();
    s = 0.f; s2 = 0.f;
#pragma unroll
    for (int i = 0; i < 8; i++) { s += rs[i]; s2 += rq[i]; }
    const float mean = s * (1.f / DM);
    const float var  = s2 * (1.f / DM) - mean * mean;
    const float rstd = rsqrtf(var + 1e-5f);
    __nv_bfloat16* orow = out + (size_t)row * DM;
#pragma unroll
    for (int i = 0; i < 4; i++) {
        const int c = tid + 256 * i;
        orow[c] = __float2bfloat16((v[i] - mean) * rstd * gamma[c] + beta[c]);
    }
}

// ---------------- transpose body ----------------
__device__ __forceinline__ void transpose_tile(const float* in, __nv_bfloat16* out,
                                               int K, int Nsrc, int Nout,
                                               int kb, int nb, int tx, int ty) {
    __shared__ float t[32][33];
#pragma unroll
    for (int j = ty; j < 32; j += 8) {
        const int n = nb + tx;
        t[j][tx] = (n < Nsrc) ? in[(size_t)(kb + j) * Nsrc + n] : 0.f;
    }
    __syncthreads();
#pragma unroll
    for (int j = ty; j < 32; j += 8) {
        const int n = nb + j;
        if (n < Nout) out[(size_t)n * K + kb + tx] = __float2bfloat16(t[tx][j]);
    }
}

__global__ void transpose_bf_kernel(const float* __restrict__ in,
                                    __nv_bfloat16* __restrict__ out,
                                    int K, int Nsrc, int Nout) {
    transpose_tile(in, out, K, Nsrc, Nout,
                   blockIdx.x * 32, blockIdx.y * 32, threadIdx.x, threadIdx.y);
}

// merged: W_out (2048 blocks), W_xp (256), W_dt (128)
__global__ void transpose_rest_kernel(const float* __restrict__ Wout,
                                      const float* __restrict__ Wxp,
                                      const float* __restrict__ Wdt,
                                      __nv_bfloat16* __restrict__ o1,
                                      __nv_bfloat16* __restrict__ o2,
                                      __nv_bfloat16* __restrict__ o3) {
    const int b = blockIdx.x;
    const int tx = threadIdx.x, ty = threadIdx.y;
    if (b < 2048) {
        transpose_tile(Wout, o1, DI, DM, DM, (b & 63) * 32, (b >> 6) * 32, tx, ty);
    } else if (b < 2304) {
        const int b2 = b - 2048;
        transpose_tile(Wxp, o2, DI, GDIM, GP, (b2 & 63) * 32, (b2 >> 6) * 32, tx, ty);
    } else {
        const int b3 = b - 2304;
        transpose_tile(Wdt, o3, RANK, DI, DI, (b3 & 1) * 32, (b3 >> 1) * 32, tx, ty);
    }
}

// ---------------- conv + silu (bf16 in, bf16 out) ----------------
__global__ void conv_silu_kernel(const __nv_bfloat16* __restrict__ xz,
                                 const float* __restrict__ w,
                                 const float* __restrict__ bias,
                                 __nv_bfloat16* __restrict__ ubf) {
    const int idx = blockIdx.x * blockDim.x + threadIdx.x;
    const int d  = idx & (DI - 1);
    const int bl = idx >> 11;
    const int l  = bl & (LSEQ - 1);
    float acc = bias[d];
#pragma unroll
    for (int j = 0; j < DC; j++) {
        const int lj = l - (DC - 1) + j;
        if (lj >= 0)
            acc = fmaf(w[d * DC + j],
                       __bfloat162float(xz[(size_t)(bl - (DC - 1) + j) * (2 * DI) + d]), acc);
    }
    const float sig = 1.f / (1.f + __expf(-acc));
    ubf[idx] = __float2bfloat16(acc * sig);
}

// ---------------- bf16 mma.sync GEMM with ldmatrix ----------------
// C[M,N] = A[M,K] @ Bt[N,K]^T ; A,Bt bf16; C fp32 or bf16 (OBF).
// EPI: 0 none | 1 softplus(acc+E[col]) | 2 acc+E[r*ldc+c]
template <int EPI, bool OBF>
__global__ __launch_bounds__(256, 2)
void mma_gemm_kernel(const __nv_bfloat16* __restrict__ A,
                     const __nv_bfloat16* __restrict__ Bt,
                     void* __restrict__ Cv, int M, int N,
                     int lda, int ldb, int ldc, const float* __restrict__ E,
                     int Kloc, size_t partStride) {
    constexpr int BM = 128, BN = 128, BK = 64;
    constexpr int STAGE_BYTES = 2 * 128 * 128;
    constexpr int STAGES = 3;

    extern __shared__ __align__(128) char smem[];
    const uint32_t smem_b = smem_u32(smem);

    const int tid  = threadIdx.x;
    const int wid  = tid >> 5;
    const int lane = tid & 31;
    const int g    = lane >> 2;
    const int t    = lane & 3;
    const int rl   = lane & 7;
    const int l3   = (lane >> 3) & 1;
    const int l4   = lane >> 4;

    const int warpRow = wid & 1;
    const int warpCol = wid >> 1;
    const int rowBase = blockIdx.y * BM;
    const int colBase = blockIdx.x * BN;
    const int kbase   = blockIdx.z * Kloc;

    float acc[4][4][4];
#pragma unroll
    for (int i = 0; i < 4; i++)
#pragma unroll
        for (int j = 0; j < 4; j++)
#pragma unroll
            for (int q = 0; q < 4; q++) acc[i][j][q] = 0.f;

    const int nchunk = Kloc / BK;

    auto load_stage = [&](int kc, int s) {
        if (kc < nchunk) {
            const uint32_t base = smem_b + (uint32_t)s * STAGE_BYTES;
            const int rw = wid * 4 + (lane >> 3);
            const int un = lane & 7;
#pragma unroll
            for (int it = 0; it < 4; it++) {
                const int r = it * 32 + rw;
                const uint32_t sw = (uint32_t)((un ^ (r & 7)) << 4);
                cp16(base + (uint32_t)r * 128 + sw,
                     A + (size_t)(rowBase + r) * lda + kbase + kc * BK + un * 8);
                cp16(base + 16384u + (uint32_t)r * 128 + sw,
                     Bt + (size_t)(colBase + r) * ldb + kbase + kc * BK + un * 8);
            }
        }
        CP_COMMIT();
    };

    // ldmatrix per-thread row/col bases (swizzle low-bits = rl for all)
    uint32_t rowOffA[4], colOffB[2];
#pragma unroll
    for (int mt = 0; mt < 4; mt++)
        rowOffA[mt] = (uint32_t)(warpRow * 64 + mt * 16 + l3 * 8 + rl) * 128;
#pragma unroll
    for (int n2 = 0; n2 < 2; n2++)
        colOffB[n2] = 16384u + (uint32_t)(warpCol * 32 + n2 * 16 + l4 * 8 + rl) * 128;

    load_stage(0, 0);
    load_stage(1, 1);

    int sidx = 0;
    for (int i = 0; i < nchunk; i++) {
        CP_WAIT1();
        __syncthreads();
        int snext = sidx + 2; if (snext >= STAGES) snext -= STAGES;
        load_stage(i + 2, snext);

        const uint32_t st = smem_b + (uint32_t)sidx * STAGE_BYTES;

#pragma unroll
        for (int ks = 0; ks < 4; ks++) {
            const uint32_t offA = (uint32_t)(((ks * 2 + l4) ^ rl) << 4);
            const uint32_t offB = (uint32_t)(((ks * 2 + l3) ^ rl) << 4);
            uint32_t afr[4][4], bfr[4][2];
#pragma unroll
            for (int mt = 0; mt < 4; mt++)
                LDSM4(afr[mt][0], afr[mt][1], afr[mt][2], afr[mt][3],
                      st + rowOffA[mt] + offA);
#pragma unroll
            for (int n2 = 0; n2 < 2; n2++)
                LDSM4(bfr[2 * n2][0], bfr[2 * n2][1], bfr[2 * n2 + 1][0], bfr[2 * n2 + 1][1],
                      st + colOffB[n2] + offB);
#pragma unroll
            for (int mt = 0; mt < 4; mt++)
#pragma unroll
                for (int nt = 0; nt < 4; nt++)
                    mma_bf16(acc[mt][nt], afr[mt], bfr[nt]);
        }
        sidx++; if (sidx >= STAGES) sidx -= STAGES;
    }

    // ---------------- epilogue ----------------
    const int rW = rowBase + warpRow * 64;
    const int cW = colBase + warpCol * 32;
#pragma unroll
    for (int mt = 0; mt < 4; mt++) {
#pragma unroll
        for (int nt = 0; nt < 4; nt++) {
            const int r0 = rW + mt * 16 + g;
            const int r1 = r0 + 8;
            const int c0 = cW + nt * 8 + 2 * t;
            float v0 = acc[mt][nt][0], v1 = acc[mt][nt][1];
            float v2 = acc[mt][nt][2], v3 = acc[mt][nt][3];
            if (EPI == 1) {
                const float b0 = E[c0], b1 = E[c0 + 1];
                v0 = softplus_f(v0 + b0);
                v1 = softplus_f(v1 + b1);
                v2 = softplus_f(v2 + b0);
                v3 = softplus_f(v3 + b1);
            } else if (EPI == 2) {
                const float2 e0 = *(const float2*)(E + (size_t)r0 * ldc + c0);
                const float2 e1 = *(const float2*)(E + (size_t)r1 * ldc + c0);
                v0 += e0.x; v1 += e0.y; v2 += e1.x; v3 += e1.y;
            }
            if (OBF) {
                __nv_bfloat16* C = (__nv_bfloat16*)Cv + (size_t)blockIdx.z * partStride;
                *(__nv_bfloat162*)(C + (size_t)r0 * ldc + c0) =
                    __nv_bfloat162(__float2bfloat16(v0), __float2bfloat16(v1));
                *(__nv_bfloat162*)(C + (size_t)r1 * ldc + c0) =
                    __nv_bfloat162(__float2bfloat16(v2), __float2bfloat16(v3));
            } else {
                float* C = (float*)Cv + (size_t)blockIdx.z * partStride;
                *(float2*)(C + (size_t)r0 * ldc + c0) = make_float2(v0, v1);
                *(float2*)(C + (size_t)r1 * ldc + c0) = make_float2(v2, v3);
            }
        }
    }
}

// ---------------- split-K reduce + dt->bf16 ----------------
__global__ void reduce_xdbl_kernel(const float* __restrict__ part,
                                   float* __restrict__ xdbl,
                                   __nv_bfloat16* __restrict__ dtbf) {
    const int idx = blockIdx.x * blockDim.x + threadIdx.x;
    const size_t S = (size_t)BL * GP;
    float s = part[idx] + part[idx + S] + part[idx + 2 * S] + part[idx + 3 * S];
    xdbl[idx] = s;
    const int col = idx & (GP - 1);
    if (col < RANK) dtbf[(size_t)(idx >> 7) * RANK + col] = __float2bfloat16(s);
}

// ---------------- scan pass A ----------------
__global__ void scanA_kernel(const float* __restrict__ delta,
                             const __nv_bfloat16* __restrict__ u,
                             const float* __restrict__ xdbl,
                             const float* __restrict__ A_log,
                             float* __restrict__ S, float* __restrict__ dsum) {
    __shared__ float Bs[CHL * DS];
    const int tid = threadIdx.x;
    const int d = blockIdx.x * 128 + tid;
    const int c = blockIdx.y, b = blockIdx.z;
    const int l0 = c * CHL;

    for (int i = tid; i < CHL * DS; i += 128) {
        const int l = i >> 4, n = i & 15;
        Bs[i] = xdbl[((size_t)(b * LSEQ + l0 + l)) * GP + RANK + n];
    }

    float Av[DS];
#pragma unroll
    for (int n = 0; n < DS; n++) Av[n] = -__expf(A_log[d * DS + n]);
    bool structured = (Av[0] < 0.f);
#pragma unroll
    for (int n = 1; n < DS; n++)
        structured = structured && (fabsf(Av[n] - (n + 1) * Av[0]) <= 1e-5f * fabsf(Av[n]));
    __syncthreads();

    float h[DS];
#pragma unroll
    for (int n = 0; n < DS; n++) h[n] = 0.f;
    float ds = 0.f;

    size_t p = ((size_t)(b * LSEQ + l0)) * DI + d;
    for (int l = 0; l < CHL; l++, p += DI) {
        const float dv = delta[p];
        const float uv = __bfloat162float(u[p]);
        ds += dv;
        const float cv = dv * uv;
        float pw[DS];
        if (structured) {
            powers16(__expf(dv * Av[0]), pw);
        } else {
#pragma unroll
            for (int n = 0; n < DS; n++) pw[n] = __expf(dv * Av[n]);
        }
#pragma unroll
        for (int n = 0; n < DS; n++)
            h[n] = fmaf(pw[n], h[n], cv * Bs[l * DS + n]);
    }

    const size_t o = ((size_t)((b * NCH + c) * DI) + d) * DS;
#pragma unroll
    for (int n = 0; n < DS; n++) S[o + n] = h[n];
    dsum[(size_t)(b * NCH + c) * DI + d] = ds;
}

// ---------------- scan pass B ----------------
__global__ void scanB_kernel(const float* __restrict__ S,
                             const float* __restrict__ dsum,
                             const float* __restrict__ A_log,
                             float* __restrict__ H0) {
    const int idx = blockIdx.x * blockDim.x + threadIdx.x;
    const int n = idx & 15;
    const int d = (idx >> 4) & (DI - 1);
    const int b = idx >> 15;
    const float Av = -__expf(A_log[d * DS + n]);
    float h = 0.f;
#pragma unroll
    for (int c = 0; c < NCH; c++) {
        const size_t o = ((size_t)((b * NCH + c) * DI) + d) * DS + n;
        H0[o] = h;
        const float P = __expf(dsum[(size_t)(b * NCH + c) * DI + d] * Av);
        h = fmaf(P, h, S[o]);
    }
}

// ---------------- scan pass C ----------------
__global__ void scanC_kernel(const float* __restrict__ delta,
                             const __nv_bfloat16* __restrict__ u,
                             const float* __restrict__ xdbl,
                             const __nv_bfloat16* __restrict__ xz,
                             const float* __restrict__ A_log,
                             const float* __restrict__ Dskip,
                             const float* __restrict__ H0,
                             __nv_bfloat16* __restrict__ yg) {
    __shared__ float Bs[CHL * DS];
    __shared__ float Cs[CHL * DS];
    const int tid = threadIdx.x;
    const int d = blockIdx.x * 128 + tid;
    const int c = blockIdx.y, b = blockIdx.z;
    const int l0 = c * CHL;

    for (int i = tid; i < CHL * DS; i += 128) {
        const int l = i >> 4, n = i & 15;
        const size_t row = ((size_t)(b * LSEQ + l0 + l)) * GP + RANK;
        Bs[i] = xdbl[row + n];
        Cs[i] = xdbl[row + DS + n];
    }

    float Av[DS];
#pragma unroll
    for (int n = 0; n < DS; n++) Av[n] = -__expf(A_log[d * DS + n]);
    bool structured = (Av[0] < 0.f);
#pragma unroll
    for (int n = 1; n < DS; n++)
        structured = structured && (fabsf(Av[n] - (n + 1) * Av[0]) <= 1e-5f * fabsf(Av[n]));
    const float dsk = Dskip[d];
    __syncthreads();

    float h[DS];
    const size_t ho = ((size_t)((b * NCH + c) * DI) + d) * DS;
#pragma unroll
    for (int n = 0; n < DS; n++) h[n] = H0[ho + n];

    size_t p = ((size_t)(b * LSEQ + l0)) * DI + d;
    for (int l = 0; l < CHL; l++, p += DI) {
        const float dv = delta[p];
        const float uv = __bfloat162float(u[p]);
        const float zv = __bfloat162float(xz[((size_t)(b * LSEQ + l0 + l)) * (2 * DI) + DI + d]);
        const float cv = dv * uv;
        float pw[DS];
        if (structured) {
            powers16(__expf(dv * Av[0]), pw);
        } else {
#pragma unroll
            for (int n = 0; n < DS; n++) pw[n] = __expf(dv * Av[n]);
        }
        float y0 = 0.f, y1 = 0.f, y2 = 0.f, y3 = 0.f;
#pragma unroll
        for (int n = 0; n < DS; n += 4) {
            h[n]     = fmaf(pw[n],     h[n],     cv * Bs[l * DS + n]);
            h[n + 1] = fmaf(pw[n + 1], h[n + 1], cv * Bs[l * DS + n + 1]);
            h[n + 2] = fmaf(pw[n + 2], h[n + 2], cv * Bs[l * DS + n + 2]);
            h[n + 3] = fmaf(pw[n + 3], h[n + 3], cv * Bs[l * DS + n + 3]);
            y0 = fmaf(h[n],     Cs[l * DS + n],     y0);
            y1 = fmaf(h[n + 1], Cs[l * DS + n + 1], y1);
            y2 = fmaf(h[n + 2], Cs[l * DS + n + 2], y2);
            y3 = fmaf(h[n + 3], Cs[l * DS + n + 3], y3);
        }
        const float y = (y0 + y1) + (y2 + y3) + uv * dsk;
        const float sig = 1.f / (1.f + __expf(-zv));
        yg[p] = __float2bfloat16(y * (zv * sig));
    }
}

// ---------------- launch ----------------
extern "C" void kernel_launch(void* const* d_in, const int* in_sizes, int n_in,
                              void* d_out, int out_size) {
    const float* x       = (const float*)d_in[0];
    const float* ln_g    = (const float*)d_in[1];
    const float* ln_b    = (const float*)d_in[2];
    const float* W_in    = (const float*)d_in[3];
    const float* conv_w  = (const float*)d_in[4];
    const float* conv_b  = (const float*)d_in[5];
    const float* W_xproj = (const float*)d_in[6];
    const float* W_dt    = (const float*)d_in[7];
    const float* b_dt    = (const float*)d_in[8];
    const float* A_log   = (const float*)d_in[9];
    const float* D_skip  = (const float*)d_in[10];
    const float* W_out   = (const float*)d_in[11];
    float* out = (float*)d_out;

    __nv_bfloat16 *xn, *xzbf, *ubf, *dtbf, *yg, *wtin, *wtout, *wtxp, *wtdt;
    float *part, *xdbl, *delta, *Sb, *H0b, *dsumb;
    cudaGetSymbolAddress((void**)&xn,    g_xn_bf);
    cudaGetSymbolAddress((void**)&xzbf,  g_xz_bf);
    cudaGetSymbolAddress((void**)&ubf,   g_u_bf);
    cudaGetSymbolAddress((void**)&part,  g_part);
    cudaGetSymbolAddress((void**)&xdbl,  g_xdbl);
    cudaGetSymbolAddress((void**)&dtbf,  g_dt_bf);
    cudaGetSymbolAddress((void**)&delta, g_delta);
    cudaGetSymbolAddress((void**)&yg,    g_yg_bf);
    cudaGetSymbolAddress((void**)&Sb,    g_S);
    cudaGetSymbolAddress((void**)&H0b,   g_H0);
    cudaGetSymbolAddress((void**)&dsumb, g_dsum);
    cudaGetSymbolAddress((void**)&wtin,  g_wt_in);
    cudaGetSymbolAddress((void**)&wtout, g_wt_out);
    cudaGetSymbolAddress((void**)&wtxp,  g_wt_xp);
    cudaGetSymbolAddress((void**)&wtdt,  g_wt_dt);

    const int smemBytes = 3 * 2 * 128 * 128;   // 98304
    cudaFuncSetAttribute(mma_gemm_kernel<0, true>,  cudaFuncAttributeMaxDynamicSharedMemorySize, smemBytes);
    cudaFuncSetAttribute(mma_gemm_kernel<0, false>, cudaFuncAttributeMaxDynamicSharedMemorySize, smemBytes);
    cudaFuncSetAttribute(mma_gemm_kernel<1, false>, cudaFuncAttributeMaxDynamicSharedMemorySize, smemBytes);
    cudaFuncSetAttribute(mma_gemm_kernel<2, false>, cudaFuncAttributeMaxDynamicSharedMemorySize, smemBytes);

    dim3 tb(32, 8);

    // 1) transpose W_in
    transpose_bf_kernel<<<dim3(DM / 32, (2 * DI) / 32), tb>>>(W_in, wtin, DM, 2 * DI, 2 * DI);
    // 2) layernorm
    ln_kernel<<<BL, 256>>>(x, ln_g, ln_b, xn);
    // 3) remaining transposes (merged)
    transpose_rest_kernel<<<2432, tb>>>(W_out, W_xproj, W_dt, wtout, wtxp, wtdt);
    // 4) xz = xn @ W_in -> bf16  (PROFILED)
    mma_gemm_kernel<0, true><<<dim3((2 * DI) / 128, BL / 128, 1), 256, smemBytes>>>(
        xn, wtin, xzbf, BL, 2 * DI, DM, DM, 2 * DI, nullptr, DM, 0);
    // 5) conv + silu (bf16)
    conv_silu_kernel<<<((size_t)BL * DI) / 256, 256>>>(xzbf, conv_w, conv_b, ubf);
    // 6) x_dbl partials (split-K)
    mma_gemm_kernel<0, false><<<dim3(GP / 128, BL / 128, SPLITK), 256, smemBytes>>>(
        ubf, wtxp, part, BL, GP, DI, DI, GP, nullptr, DI / SPLITK, (size_t)BL * GP);
    // 7) reduce
    reduce_xdbl_kernel<<<(BL * GP) / 256, 256>>>(part, xdbl, dtbf);
    // 8) delta
    mma_gemm_kernel<1, false><<<dim3(DI / 128, BL / 128, 1), 256, smemBytes>>>(
        dtbf, wtdt, delta, BL, DI, RANK, RANK, DI, b_dt, RANK, 0);
    // 9-11) chunked selective scan
    scanA_kernel<<<dim3(DI / 128, NCH, BATCH), 128>>>(delta, ubf, xdbl, A_log, Sb, dsumb);
    scanB_kernel<<<(BATCH * DI * DS) / 256, 256>>>(Sb, dsumb, A_log, H0b);
    scanC_kernel<<<dim3(DI / 128, NCH, BATCH), 128>>>(delta, ubf, xdbl, xzbf, A_log, D_skip, H0b, yg);
    // 12) out = x + yg @ W_out
    mma_gemm_kernel<2, false><<<dim3(DM / 128, BL / 128, 1), 256, smemBytes>>>(
        yg, wtout, out, BL, DM, DI, DI, DM, x, DI, 0);
}

// round 8
// speedup vs baseline: 13.3821x; 1.1484x over previous
#include <cuda_runtime.h>
#include <cuda_bf16.h>
#include <math.h>
#include <stdint.h>

// ---------------- problem constants ----------------
#define BATCH   2
#define LSEQ    2048
#define DM      1024
#define DI      2048
#define DS      16
#define DC      4
#define RANK    64
#define GDIM    96
#define GP      128
#define BL      (BATCH*LSEQ)  // 4096
#define SPLITK  4
#define NCH     16
#define CHL     (LSEQ/NCH)    // 128

// ---------------- scratch ----------------
__device__ __nv_bfloat16 g_xn_bf  [(size_t)BL*DM];
__device__ __nv_bfloat16 g_xz_bf  [(size_t)BL*2*DI];
__device__ __nv_bfloat16 g_u_bf   [(size_t)BL*DI];
__device__ float         g_part   [(size_t)SPLITK*BL*GP];
__device__ float         g_xdbl   [(size_t)BL*GP];
__device__ __nv_bfloat16 g_dt_bf  [(size_t)BL*RANK];
__device__ __nv_bfloat16 g_del_bf [(size_t)BL*DI];
__device__ __nv_bfloat16 g_yg_bf  [(size_t)BL*DI];
__device__ float         g_S      [(size_t)BATCH*NCH*DI*DS];
__device__ float         g_H0     [(size_t)BATCH*NCH*DI*DS];
__device__ float         g_dsum   [(size_t)BATCH*NCH*DI];
__device__ __nv_bfloat16 g_wt_in  [(size_t)(2*DI)*DM];
__device__ __nv_bfloat16 g_wt_out [(size_t)DM*DI];
__device__ __nv_bfloat16 g_wt_xp  [(size_t)GP*DI];
__device__ __nv_bfloat16 g_wt_dt  [(size_t)DI*RANK];

// ---------------- helpers ----------------
__device__ __forceinline__ uint32_t smem_u32(const void* p) {
    uint32_t a;
    asm("{ .reg .u64 t; cvta.to.shared.u64 t, %1; cvt.u32.u64 %0, t; }" : "=r"(a) : "l"(p));
    return a;
}
__device__ __forceinline__ void cp16(uint32_t dst, const void* src) {
    asm volatile("cp.async.cg.shared.global [%0], [%1], 16;" :: "r"(dst), "l"(src));
}
#define CP_COMMIT() asm volatile("cp.async.commit_group;")
#define CP_WAIT1()  asm volatile("cp.async.wait_group 1;")

__device__ __forceinline__ void mma_bf16(float* c, const uint32_t* a, const uint32_t* b) {
    asm volatile(
        "mma.sync.aligned.m16n8k16.row.col.f32.bf16.bf16.f32 "
        "{%0,%1,%2,%3}, {%4,%5,%6,%7}, {%8,%9}, {%0,%1,%2,%3};"
        : "+f"(c[0]), "+f"(c[1]), "+f"(c[2]), "+f"(c[3])
        : "r"(a[0]), "r"(a[1]), "r"(a[2]), "r"(a[3]), "r"(b[0]), "r"(b[1]));
}
#define LDSM4(r0, r1, r2, r3, addr) \
    asm volatile("ldmatrix.sync.aligned.m8n8.x4.shared.b16 {%0,%1,%2,%3}, [%4];" \
        : "=r"(r0), "=r"(r1), "=r"(r2), "=r"(r3) : "r"(addr))

__device__ __forceinline__ float softplus_f(float t) {
    return (t > 20.f) ? t : __logf(1.f + __expf(t));
}
__device__ __forceinline__ void powers16(float w, float* pw) {
    const float w2 = w * w, w4 = w2 * w2, w8 = w4 * w4;
    pw[0]  = w;        pw[1]  = w2;       pw[2]  = w2 * w;   pw[3]  = w4;
    pw[4]  = w4 * w;   pw[5]  = w4 * w2;  pw[6]  = w4 * pw[2]; pw[7] = w8;
    pw[8]  = w8 * w;   pw[9]  = w8 * w2;  pw[10] = w8 * pw[2]; pw[11] = w8 * w4;
    pw[12] = w8 * pw[4]; pw[13] = w8 * pw[5]; pw[14] = w8 * pw[6]; pw[15] = w8 * w8;
}

// ---------------- prep: all weight transposes + layernorm, one launch -------
__device__ __forceinline__ void transpose64(const float* in, __nv_bfloat16* out,
                                            int K, int Nsrc, int Nout,
                                            int kb, int nb, int tx, int ty,
                                            float (*t)[33]) {
#pragma unroll
    for (int r = ty; r < 64; r += 8) {
        const int n = nb + tx;
        t[r][tx] = (n < Nsrc) ? in[(size_t)(kb + r) * Nsrc + n] : 0.f;
    }
    __syncthreads();
#pragma unroll
    for (int j = ty; j < 32; j += 8) {
        const int n = nb + j;
        if (n < Nout) {
            const __nv_bfloat162 v = __floats2bfloat162_rn(t[tx * 2][j], t[tx * 2 + 1][j]);
            *(__nv_bfloat162*)(out + (size_t)n * K + kb + tx * 2) = v;
        }
    }
}

__global__ void prep_kernel(const float* __restrict__ x,
                            const float* __restrict__ gamma,
                            const float* __restrict__ beta,
                            const float* __restrict__ Win,
                            const float* __restrict__ Wout,
                            const float* __restrict__ Wxp,
                            const float* __restrict__ Wdt,
                            __nv_bfloat16* __restrict__ xn,
                            __nv_bfloat16* __restrict__ wtin,
                            __nv_bfloat16* __restrict__ wtout,
                            __nv_bfloat16* __restrict__ wtxp,
                            __nv_bfloat16* __restrict__ wtdt) {
    __shared__ float t[64][33];
    const int tx = threadIdx.x, ty = threadIdx.y;
    int b = blockIdx.x;
    if (b < 2048) {
        transpose64(Win, wtin, DM, 2 * DI, 2 * DI, (b & 15) * 64, (b >> 4) * 32, tx, ty, t);
    } else if (b < 3072) {
        b -= 2048;
        transpose64(Wout, wtout, DI, DM, DM, (b & 31) * 64, (b >> 5) * 32, tx, ty, t);
    } else if (b < 3200) {
        b -= 3072;
        transpose64(Wxp, wtxp, DI, GDIM, GP, (b & 31) * 64, (b >> 5) * 32, tx, ty, t);
    } else if (b < 3264) {
        b -= 3200;
        transpose64(Wdt, wtdt, RANK, DI, DI, 0, b * 32, tx, ty, t);
    } else {
        const int row = b - 3264;
        const int tid = ty * 32 + tx;
        const float4 v = ((const float4*)(x + (size_t)row * DM))[tid];
        float s  = v.x + v.y + v.z + v.w;
        float s2 = v.x * v.x + v.y * v.y + v.z * v.z + v.w * v.w;
#pragma unroll
        for (int o = 16; o > 0; o >>= 1) {
            s  += __shfl_xor_sync(0xffffffffu, s,  o);
            s2 += __shfl_xor_sync(0xffffffffu, s2, o);
        }
        if ((tid & 31) == 0) { t[0][tid >> 5] = s; t[1][tid >> 5] = s2; }
        __syncthreads();
        s = 0.f; s2 = 0.f;
#pragma unroll
        for (int i = 0; i < 8; i++) { s += t[0][i]; s2 += t[1][i]; }
        const float mean = s * (1.f / DM);
        const float var  = s2 * (1.f / DM) - mean * mean;
        const float rstd = rsqrtf(var + 1e-5f);
        const float4 gm = ((const float4*)gamma)[tid];
        const float4 bt = ((const float4*)beta)[tid];
        __nv_bfloat16* orow = xn + (size_t)row * DM + tid * 4;
        *(__nv_bfloat162*)(orow) =
            __floats2bfloat162_rn((v.x - mean) * rstd * gm.x + bt.x,
                                  (v.y - mean) * rstd * gm.y + bt.y);
        *(__nv_bfloat162*)(orow + 2) =
            __floats2bfloat162_rn((v.z - mean) * rstd * gm.z + bt.z,
                                  (v.w - mean) * rstd * gm.w + bt.w);
    }
}

// ---------------- conv + silu (8 channels/thread, vectorized) ----------------
__global__ void conv_silu_kernel(const __nv_bfloat16* __restrict__ xz,
                                 const float* __restrict__ w,
                                 const float* __restrict__ bias,
                                 __nv_bfloat16* __restrict__ ubf) {
    const int idx = blockIdx.x * blockDim.x + threadIdx.x;  // BL*DI/8
    const int dg = idx & 255;
    const int bl = idx >> 8;
    const int l  = bl & (LSEQ - 1);
    const int d0 = dg << 3;

    float acc[8];
    {
        const float4 b0 = *(const float4*)(bias + d0);
        const float4 b1 = *(const float4*)(bias + d0 + 4);
        acc[0] = b0.x; acc[1] = b0.y; acc[2] = b0.z; acc[3] = b0.w;
        acc[4] = b1.x; acc[5] = b1.y; acc[6] = b1.z; acc[7] = b1.w;
    }
    float wv[4][8];
#pragma unroll
    for (int k = 0; k < 8; k++) {
        const float4 wk = *(const float4*)(w + (d0 + k) * 4);
        wv[0][k] = wk.x; wv[1][k] = wk.y; wv[2][k] = wk.z; wv[3][k] = wk.w;
    }
#pragma unroll
    for (int j = 0; j < DC; j++) {
        const int lj = l - 3 + j;
        if (lj >= 0) {
            const uint4 q = *(const uint4*)(xz + (size_t)(bl - 3 + j) * (2 * DI) + d0);
            const __nv_bfloat162* h = (const __nv_bfloat162*)&q;
#pragma unroll
            for (int k2 = 0; k2 < 4; k2++) {
                const float2 f = __bfloat1622float2(h[k2]);
                acc[k2 * 2]     = fmaf(wv[j][k2 * 2],     f.x, acc[k2 * 2]);
                acc[k2 * 2 + 1] = fmaf(wv[j][k2 * 2 + 1], f.y, acc[k2 * 2 + 1]);
            }
        }
    }
    uint4 oq;
    __nv_bfloat162* oh = (__nv_bfloat162*)&oq;
#pragma unroll
    for (int k2 = 0; k2 < 4; k2++) {
        const float a0 = acc[k2 * 2],     s0 = a0 / (1.f + __expf(-a0));
        const float a1 = acc[k2 * 2 + 1], s1 = a1 / (1.f + __expf(-a1));
        oh[k2] = __floats2bfloat162_rn(s0, s1);
    }
    *(uint4*)(ubf + (size_t)bl * DI + d0) = oq;
}

// ---------------- bf16 mma.sync GEMM with ldmatrix ----------------
// C[M,N] = A[M,K] @ Bt[N,K]^T ; EPI: 0 none | 1 softplus(acc+E[col]) | 2 acc+E
template <int EPI, bool OBF>
__global__ __launch_bounds__(256, 2)
void mma_gemm_kernel(const __nv_bfloat16* __restrict__ A,
                     const __nv_bfloat16* __restrict__ Bt,
                     void* __restrict__ Cv, int M, int N,
                     int lda, int ldb, int ldc, const float* __restrict__ E,
                     int Kloc, size_t partStride) {
    constexpr int BM = 128, BN = 128, BK = 64;
    constexpr int STAGE_BYTES = 2 * 128 * 128;
    constexpr int STAGES = 3;

    extern __shared__ __align__(128) char smem[];
    const uint32_t smem_b = smem_u32(smem);

    const int tid  = threadIdx.x;
    const int wid  = tid >> 5;
    const int lane = tid & 31;
    const int g    = lane >> 2;
    const int t    = lane & 3;
    const int rl   = lane & 7;
    const int l3   = (lane >> 3) & 1;
    const int l4   = lane >> 4;

    const int warpRow = wid & 1;
    const int warpCol = wid >> 1;
    const int rowBase = blockIdx.y * BM;
    const int colBase = blockIdx.x * BN;
    const int kbase   = blockIdx.z * Kloc;

    float acc[4][4][4];
#pragma unroll
    for (int i = 0; i < 4; i++)
#pragma unroll
        for (int j = 0; j < 4; j++)
#pragma unroll
            for (int q = 0; q < 4; q++) acc[i][j][q] = 0.f;

    const int nchunk = Kloc / BK;

    auto load_stage = [&](int kc, int s) {
        if (kc < nchunk) {
            const uint32_t base = smem_b + (uint32_t)s * STAGE_BYTES;
            const int rw = wid * 4 + (lane >> 3);
            const int un = lane & 7;
#pragma unroll
            for (int it = 0; it < 4; it++) {
                const int r = it * 32 + rw;
                const uint32_t sw = (uint32_t)((un ^ (r & 7)) << 4);
                cp16(base + (uint32_t)r * 128 + sw,
                     A + (size_t)(rowBase + r) * lda + kbase + kc * BK + un * 8);
                cp16(base + 16384u + (uint32_t)r * 128 + sw,
                     Bt + (size_t)(colBase + r) * ldb + kbase + kc * BK + un * 8);
            }
        }
        CP_COMMIT();
    };

    uint32_t rowOffA[4], colOffB[2];
#pragma unroll
    for (int mt = 0; mt < 4; mt++)
        rowOffA[mt] = (uint32_t)(warpRow * 64 + mt * 16 + l3 * 8 + rl) * 128;
#pragma unroll
    for (int n2 = 0; n2 < 2; n2++)
        colOffB[n2] = 16384u + (uint32_t)(warpCol * 32 + n2 * 16 + l4 * 8 + rl) * 128;

    load_stage(0, 0);
    load_stage(1, 1);

    int sidx = 0;
    for (int i = 0; i < nchunk; i++) {
        CP_WAIT1();
        __syncthreads();
        int snext = sidx + 2; if (snext >= STAGES) snext -= STAGES;
        load_stage(i + 2, snext);

        const uint32_t st = smem_b + (uint32_t)sidx * STAGE_BYTES;

#pragma unroll
        for (int ks = 0; ks < 4; ks++) {
            const uint32_t offA = (uint32_t)(((ks * 2 + l4) ^ rl) << 4);
            const uint32_t offB = (uint32_t)(((ks * 2 + l3) ^ rl) << 4);
            uint32_t afr[4][4], bfr[4][2];
#pragma unroll
            for (int mt = 0; mt < 4; mt++)
                LDSM4(afr[mt][0], afr[mt][1], afr[mt][2], afr[mt][3],
                      st + rowOffA[mt] + offA);
#pragma unroll
            for (int n2 = 0; n2 < 2; n2++)
                LDSM4(bfr[2 * n2][0], bfr[2 * n2][1], bfr[2 * n2 + 1][0], bfr[2 * n2 + 1][1],
                      st + colOffB[n2] + offB);
#pragma unroll
            for (int mt = 0; mt < 4; mt++)
#pragma unroll
                for (int nt = 0; nt < 4; nt++)
                    mma_bf16(acc[mt][nt], afr[mt], bfr[nt]);
        }
        sidx++; if (sidx >= STAGES) sidx -= STAGES;
    }

    const int rW = rowBase + warpRow * 64;
    const int cW = colBase + warpCol * 32;
#pragma unroll
    for (int mt = 0; mt < 4; mt++) {
#pragma unroll
        for (int nt = 0; nt < 4; nt++) {
            const int r0 = rW + mt * 16 + g;
            const int r1 = r0 + 8;
            const int c0 = cW + nt * 8 + 2 * t;
            float v0 = acc[mt][nt][0], v1 = acc[mt][nt][1];
            float v2 = acc[mt][nt][2], v3 = acc[mt][nt][3];
            if (EPI == 1) {
                const float b0 = E[c0], b1 = E[c0 + 1];
                v0 = softplus_f(v0 + b0);
                v1 = softplus_f(v1 + b1);
                v2 = softplus_f(v2 + b0);
                v3 = softplus_f(v3 + b1);
            } else if (EPI == 2) {
                const float2 e0 = *(const float2*)(E + (size_t)r0 * ldc + c0);
                const float2 e1 = *(const float2*)(E + (size_t)r1 * ldc + c0);
                v0 += e0.x; v1 += e0.y; v2 += e1.x; v3 += e1.y;
            }
            if (OBF) {
                __nv_bfloat16* C = (__nv_bfloat16*)Cv + (size_t)blockIdx.z * partStride;
                *(__nv_bfloat162*)(C + (size_t)r0 * ldc + c0) = __floats2bfloat162_rn(v0, v1);
                *(__nv_bfloat162*)(C + (size_t)r1 * ldc + c0) = __floats2bfloat162_rn(v2, v3);
            } else {
                float* C = (float*)Cv + (size_t)blockIdx.z * partStride;
                *(float2*)(C + (size_t)r0 * ldc + c0) = make_float2(v0, v1);
                *(float2*)(C + (size_t)r1 * ldc + c0) = make_float2(v2, v3);
            }
        }
    }
}

// ---------------- split-K reduce (float4) + dt->bf16 ----------------
__global__ void reduce_xdbl_kernel(const float* __restrict__ part,
                                   float* __restrict__ xdbl,
                                   __nv_bfloat16* __restrict__ dtbf) {
    const int i4 = blockIdx.x * blockDim.x + threadIdx.x;    // BL*GP/4
    const size_t S4 = (size_t)BL * GP / 4;
    const float4* p4 = (const float4*)part;
    const float4 a = p4[i4], b = p4[i4 + S4], c = p4[i4 + 2 * S4], d = p4[i4 + 3 * S4];
    float4 s;
    s.x = a.x + b.x + c.x + d.x;
    s.y = a.y + b.y + c.y + d.y;
    s.z = a.z + b.z + c.z + d.z;
    s.w = a.w + b.w + c.w + d.w;
    ((float4*)xdbl)[i4] = s;
    const int col = (i4 << 2) & (GP - 1);
    if (col < RANK) {
        const int row = i4 >> 5;
        __nv_bfloat16* dp = dtbf + (size_t)row * RANK + col;
        *(__nv_bfloat162*)(dp)     = __floats2bfloat162_rn(s.x, s.y);
        *(__nv_bfloat162*)(dp + 2) = __floats2bfloat162_rn(s.z, s.w);
    }
}

// ---------------- scan pass A ----------------
__global__ void scanA_kernel(const __nv_bfloat16* __restrict__ delta,
                             const __nv_bfloat16* __restrict__ u,
                             const float* __restrict__ xdbl,
                             const float* __restrict__ A_log,
                             float* __restrict__ S, float* __restrict__ dsum) {
    __shared__ float Bs[CHL * DS];
    const int tid = threadIdx.x;
    const int d = blockIdx.x * 128 + tid;
    const int c = blockIdx.y, b = blockIdx.z;
    const int l0 = c * CHL;

    const float4* xd4 = (const float4*)xdbl;
    for (int i = tid; i < CHL * 4; i += 128) {
        const int l = i >> 2, q = i & 3;
        ((float4*)Bs)[l * 4 + q] = xd4[((size_t)(b * LSEQ + l0 + l)) * 32 + 16 + q];
    }

    float Av[DS];
#pragma unroll
    for (int n = 0; n < DS; n++) Av[n] = -__expf(A_log[d * DS + n]);
    bool structured = (Av[0] < 0.f);
#pragma unroll
    for (int n = 1; n < DS; n++)
        structured = structured && (fabsf(Av[n] - (n + 1) * Av[0]) <= 1e-5f * fabsf(Av[n]));
    __syncthreads();

    float h[DS];
#pragma unroll
    for (int n = 0; n < DS; n++) h[n] = 0.f;
    float ds = 0.f;

    size_t p = ((size_t)(b * LSEQ + l0)) * DI + d;
    for (int l = 0; l < CHL; l++, p += DI) {
        const float dv = __bfloat162float(delta[p]);
        const float uv = __bfloat162float(u[p]);
        ds += dv;
        const float cv = dv * uv;
        float pw[DS];
        if (structured) {
            powers16(__expf(dv * Av[0]), pw);
        } else {
#pragma unroll
            for (int n = 0; n < DS; n++) pw[n] = __expf(dv * Av[n]);
        }
#pragma unroll
        for (int n = 0; n < DS; n++)
            h[n] = fmaf(pw[n], h[n], cv * Bs[l * DS + n]);
    }

    const size_t o = ((size_t)((b * NCH + c) * DI) + d) * DS;
#pragma unroll
    for (int n = 0; n < DS; n++) S[o + n] = h[n];
    dsum[(size_t)(b * NCH + c) * DI + d] = ds;
}

// ---------------- scan pass B ----------------
__global__ void scanB_kernel(const float* __restrict__ S,
                             const float* __restrict__ dsum,
                             const float* __restrict__ A_log,
                             float* __restrict__ H0) {
    const int idx = blockIdx.x * blockDim.x + threadIdx.x;
    const int n = idx & 15;
    const int d = (idx >> 4) & (DI - 1);
    const int b = idx >> 15;
    const float Av = -__expf(A_log[d * DS + n]);
    float h = 0.f;
#pragma unroll
    for (int c = 0; c < NCH; c++) {
        const size_t o = ((size_t)((b * NCH + c) * DI) + d) * DS + n;
        H0[o] = h;
        const float P = __expf(dsum[(size_t)(b * NCH + c) * DI + d] * Av);
        h = fmaf(P, h, S[o]);
    }
}

// ---------------- scan pass C ----------------
__global__ void scanC_kernel(const __nv_bfloat16* __restrict__ delta,
                             const __nv_bfloat16* __restrict__ u,
                             const float* __restrict__ xdbl,
                             const __nv_bfloat16* __restrict__ xz,
                             const float* __restrict__ A_log,
                             const float* __restrict__ Dskip,
                             const float* __restrict__ H0,
                             __nv_bfloat16* __restrict__ yg) {
    __shared__ float Bs[CHL * DS];
    __shared__ float Cs[CHL * DS];
    const int tid = threadIdx.x;
    const int d = blockIdx.x * 128 + tid;
    const int c = blockIdx.y, b = blockIdx.z;
    const int l0 = c * CHL;

    const float4* xd4 = (const float4*)xdbl;
    for (int i = tid; i < CHL * 4; i += 128) {
        const int l = i >> 2, q = i & 3;
        const size_t row = ((size_t)(b * LSEQ + l0 + l)) * 32;
        ((float4*)Bs)[l * 4 + q] = xd4[row + 16 + q];
        ((float4*)Cs)[l * 4 + q] = xd4[row + 20 + q];
    }

    float Av[DS];
#pragma unroll
    for (int n = 0; n < DS; n++) Av[n] = -__expf(A_log[d * DS + n]);
    bool structured = (Av[0] < 0.f);
#pragma unroll
    for (int n = 1; n < DS; n++)
        structured = structured && (fabsf(Av[n] - (n + 1) * Av[0]) <= 1e-5f * fabsf(Av[n]));
    const float dsk = Dskip[d];
    __syncthreads();

    float h[DS];
    const size_t ho = ((size_t)((b * NCH + c) * DI) + d) * DS;
#pragma unroll
    for (int n = 0; n < DS; n++) h[n] = H0[ho + n];

    size_t p = ((size_t)(b * LSEQ + l0)) * DI + d;
    for (int l = 0; l < CHL; l++, p += DI) {
        const float dv = __bfloat162float(delta[p]);
        const float uv = __bfloat162float(u[p]);
        const float zv = __bfloat162float(xz[((size_t)(b * LSEQ + l0 + l)) * (2 * DI) + DI + d]);
        const float cv = dv * uv;
        float pw[DS];
        if (structured) {
            powers16(__expf(dv * Av[0]), pw);
        } else {
#pragma unroll
            for (int n = 0; n < DS; n++) pw[n] = __expf(dv * Av[n]);
        }
        float y0 = 0.f, y1 = 0.f, y2 = 0.f, y3 = 0.f;
#pragma unroll
        for (int n = 0; n < DS; n += 4) {
            h[n]     = fmaf(pw[n],     h[n],     cv * Bs[l * DS + n]);
            h[n + 1] = fmaf(pw[n + 1], h[n + 1], cv * Bs[l * DS + n + 1]);
            h[n + 2] = fmaf(pw[n + 2], h[n + 2], cv * Bs[l * DS + n + 2]);
            h[n + 3] = fmaf(pw[n + 3], h[n + 3], cv * Bs[l * DS + n + 3]);
            y0 = fmaf(h[n],     Cs[l * DS + n],     y0);
            y1 = fmaf(h[n + 1], Cs[l * DS + n + 1], y1);
            y2 = fmaf(h[n + 2], Cs[l * DS + n + 2], y2);
            y3 = fmaf(h[n + 3], Cs[l * DS + n + 3], y3);
        }
        const float y = (y0 + y1) + (y2 + y3) + uv * dsk;
        const float sig = 1.f / (1.f + __expf(-zv));
        yg[p] = __float2bfloat16(y * (zv * sig));
    }
}

// ---------------- launch ----------------
extern "C" void kernel_launch(void* const* d_in, const int* in_sizes, int n_in,
                              void* d_out, int out_size) {
    const float* x       = (const float*)d_in[0];
    const float* ln_g    = (const float*)d_in[1];
    const float* ln_b    = (const float*)d_in[2];
    const float* W_in    = (const float*)d_in[3];
    const float* conv_w  = (const float*)d_in[4];
    const float* conv_b  = (const float*)d_in[5];
    const float* W_xproj = (const float*)d_in[6];
    const float* W_dt    = (const float*)d_in[7];
    const float* b_dt    = (const float*)d_in[8];
    const float* A_log   = (const float*)d_in[9];
    const float* D_skip  = (const float*)d_in[10];
    const float* W_out   = (const float*)d_in[11];
    float* out = (float*)d_out;

    __nv_bfloat16 *xn, *xzbf, *ubf, *dtbf, *delbf, *yg, *wtin, *wtout, *wtxp, *wtdt;
    float *part, *xdbl, *Sb, *H0b, *dsumb;
    cudaGetSymbolAddress((void**)&xn,    g_xn_bf);
    cudaGetSymbolAddress((void**)&xzbf,  g_xz_bf);
    cudaGetSymbolAddress((void**)&ubf,   g_u_bf);
    cudaGetSymbolAddress((void**)&part,  g_part);
    cudaGetSymbolAddress((void**)&xdbl,  g_xdbl);
    cudaGetSymbolAddress((void**)&dtbf,  g_dt_bf);
    cudaGetSymbolAddress((void**)&delbf, g_del_bf);
    cudaGetSymbolAddress((void**)&yg,    g_yg_bf);
    cudaGetSymbolAddress((void**)&Sb,    g_S);
    cudaGetSymbolAddress((void**)&H0b,   g_H0);
    cudaGetSymbolAddress((void**)&dsumb, g_dsum);
    cudaGetSymbolAddress((void**)&wtin,  g_wt_in);
    cudaGetSymbolAddress((void**)&wtout, g_wt_out);
    cudaGetSymbolAddress((void**)&wtxp,  g_wt_xp);
    cudaGetSymbolAddress((void**)&wtdt,  g_wt_dt);

    const int smemBytes = 3 * 2 * 128 * 128;   // 98304
    cudaFuncSetAttribute(mma_gemm_kernel<0, true>,  cudaFuncAttributeMaxDynamicSharedMemorySize, smemBytes);
    cudaFuncSetAttribute(mma_gemm_kernel<0, false>, cudaFuncAttributeMaxDynamicSharedMemorySize, smemBytes);
    cudaFuncSetAttribute(mma_gemm_kernel<1, true>,  cudaFuncAttributeMaxDynamicSharedMemorySize, smemBytes);
    cudaFuncSetAttribute(mma_gemm_kernel<2, false>, cudaFuncAttributeMaxDynamicSharedMemorySize, smemBytes);

    // 1) prep: all weight transposes + layernorm
    prep_kernel<<<3264 + BL, dim3(32, 8)>>>(x, ln_g, ln_b, W_in, W_out, W_xproj, W_dt,
                                            xn, wtin, wtout, wtxp, wtdt);
    // 2) xz = xn @ W_in -> bf16
    mma_gemm_kernel<0, true><<<dim3((2 * DI) / 128, BL / 128, 1), 256, smemBytes>>>(
        xn, wtin, xzbf, BL, 2 * DI, DM, DM, 2 * DI, nullptr, DM, 0);
    // 3) conv + silu
    conv_silu_kernel<<<((size_t)BL * DI / 8) / 256, 256>>>(xzbf, conv_w, conv_b, ubf);
    // 4) x_dbl partials (split-K)  (PROFILED)
    mma_gemm_kernel<0, false><<<dim3(GP / 128, BL / 128, SPLITK), 256, smemBytes>>>(
        ubf, wtxp, part, BL, GP, DI, DI, GP, nullptr, DI / SPLITK, (size_t)BL * GP);
    // 5) reduce
    reduce_xdbl_kernel<<<(BL * GP / 4) / 256, 256>>>(part, xdbl, dtbf);
    // 6) delta = softplus(dt @ W_dt + b_dt) -> bf16
    mma_gemm_kernel<1, true><<<dim3(DI / 128, BL / 128, 1), 256, smemBytes>>>(
        dtbf, wtdt, delbf, BL, DI, RANK, RANK, DI, b_dt, RANK, 0);
    // 7-9) chunked selective scan
    scanA_kernel<<<dim3(DI / 128, NCH, BATCH), 128>>>(delbf, ubf, xdbl, A_log, Sb, dsumb);
    scanB_kernel<<<(BATCH * DI * DS) / 256, 256>>>(Sb, dsumb, A_log, H0b);
    scanC_kernel<<<dim3(DI / 128, NCH, BATCH), 128>>>(delbf, ubf, xdbl, xzbf, A_log, D_skip, H0b, yg);
    // 10) out = x + yg @ W_out
    mma_gemm_kernel<2, false><<<dim3(DM / 128, BL / 128, 1), 256, smemBytes>>>(
        yg, wtout, out, BL, DM, DI, DI, DM, x, DI, 0);
}